// round 10
// baseline (speedup 1.0000x reference)
#include <cuda_runtime.h>
#include <cuda_bf16.h>
#include <stdint.h>
#include <math.h>

#define BB   2
#define SS   2048
#define HIDD 1024
#define NHH  16
#define HDD  64
#define MM   (BB * SS)   // 4096 rows

static constexpr size_t MH = (size_t)MM * HIDD;
static constexpr size_t HH = (size_t)HIDD * HIDD;

// ---------------------------------------------------------------------------
// Scratch (bf16 hi/lo everywhere)
// ---------------------------------------------------------------------------
__device__ __nv_bfloat16 g_inhi[3 * MH];
__device__ __nv_bfloat16 g_inlo[3 * MH];
__device__ __nv_bfloat16 g_wthi[4 * HH];
__device__ __nv_bfloat16 g_wtlo[4 * HH];
__device__ __nv_bfloat16 g_phi[3 * MH];
__device__ __nv_bfloat16 g_plo[3 * MH];
__device__ __nv_bfloat16 g_chi[MH];
__device__ __nv_bfloat16 g_clo[MH];

// ---------------------------------------------------------------------------
// PTX helpers
// ---------------------------------------------------------------------------
__device__ __forceinline__ uint32_t smem_u32(const void* p) {
    uint32_t a;
    asm("{ .reg .u64 t; cvta.to.shared.u64 t, %1; cvt.u32.u64 %0, t; }"
        : "=r"(a) : "l"(p));
    return a;
}
__device__ __forceinline__ void cp16(uint32_t saddr, const void* g) {
    asm volatile("cp.async.cg.shared.global [%0], [%1], 16;"
                 :: "r"(saddr), "l"(g) : "memory");
}
__device__ __forceinline__ void cp_commit() {
    asm volatile("cp.async.commit_group;" ::: "memory");
}
__device__ __forceinline__ void cp_wait0() {
    asm volatile("cp.async.wait_group 0;" ::: "memory");
}
__device__ __forceinline__ void ldm4(uint32_t* r, uint32_t addr) {
    asm volatile("ldmatrix.sync.aligned.m8n8.x4.shared.b16 {%0,%1,%2,%3}, [%4];"
                 : "=r"(r[0]), "=r"(r[1]), "=r"(r[2]), "=r"(r[3]) : "r"(addr));
}
__device__ __forceinline__ void ldm4t(uint32_t* r, uint32_t addr) {
    asm volatile("ldmatrix.sync.aligned.m8n8.x4.trans.shared.b16 {%0,%1,%2,%3}, [%4];"
                 : "=r"(r[0]), "=r"(r[1]), "=r"(r[2]), "=r"(r[3]) : "r"(addr));
}
__device__ __forceinline__ void mma_bf16(float* c, const uint32_t* a,
                                         const uint32_t* b) {
    asm volatile(
        "mma.sync.aligned.m16n8k16.row.col.f32.bf16.bf16.f32 "
        "{%0,%1,%2,%3}, {%4,%5,%6,%7}, {%8,%9}, {%0,%1,%2,%3};"
        : "+f"(c[0]), "+f"(c[1]), "+f"(c[2]), "+f"(c[3])
        : "r"(a[0]), "r"(a[1]), "r"(a[2]), "r"(a[3]), "r"(b[0]), "r"(b[1]));
}
// pack two floats -> bf16x2 {lo=a, hi=b} in ONE cvt
__device__ __forceinline__ uint32_t cvt2bf(float a, float b) {
    uint32_t r;
    asm("cvt.rn.bf16x2.f32 %0, %1, %2;" : "=r"(r) : "f"(b), "f"(a));
    return r;
}
// extract the two bf16 halves back to fp32 (bit shifts only)
__device__ __forceinline__ float bflo_f(uint32_t p) {
    return __uint_as_float(p << 16);
}
__device__ __forceinline__ float bfhi_f(uint32_t p) {
    return __uint_as_float(p & 0xffff0000u);
}

// ---------------------------------------------------------------------------
// Batched fp32 -> bf16 hi/lo split (3 inputs via grid.y)
// ---------------------------------------------------------------------------
__global__ __launch_bounds__(256) void split3_kernel(
    const float* __restrict__ x0, const float* __restrict__ x1,
    const float* __restrict__ x2, __nv_bfloat16* __restrict__ hiB,
    __nv_bfloat16* __restrict__ loB, int n4)
{
    int i = blockIdx.x * 256 + threadIdx.x;
    if (i >= n4) return;
    const int z = blockIdx.y;
    const float* x = (z == 0) ? x0 : (z == 1) ? x1 : x2;
    float4 v = reinterpret_cast<const float4*>(x)[i];
    uint2 ho, llo;
    ho.x  = cvt2bf(v.x, v.y);
    ho.y  = cvt2bf(v.z, v.w);
    llo.x = cvt2bf(v.x - bflo_f(ho.x), v.y - bfhi_f(ho.x));
    llo.y = cvt2bf(v.z - bflo_f(ho.y), v.w - bfhi_f(ho.y));
    size_t base = (size_t)z * (MH / 4);
    reinterpret_cast<uint2*>(hiB)[base + i] = ho;
    reinterpret_cast<uint2*>(loB)[base + i] = llo;
}

// ---------------------------------------------------------------------------
// Batched W [K][N] fp32 -> W^T [N][K] bf16 hi/lo (4 weights via grid.z)
// ---------------------------------------------------------------------------
__global__ __launch_bounds__(256) void splitT4_kernel(
    const float* __restrict__ W0, const float* __restrict__ W1,
    const float* __restrict__ W2, const float* __restrict__ W3,
    __nv_bfloat16* __restrict__ ThB, __nv_bfloat16* __restrict__ TlB)
{
    __shared__ float t[32][33];
    const int z = blockIdx.z;
    const float* W = (z == 0) ? W0 : (z == 1) ? W1 : (z == 2) ? W2 : W3;
    __nv_bfloat16* Th = ThB + (size_t)z * HH;
    __nv_bfloat16* Tl = TlB + (size_t)z * HH;
    int n0 = blockIdx.x * 32, k0 = blockIdx.y * 32;
    int tx = threadIdx.x & 31, ty = threadIdx.x >> 5;
    #pragma unroll
    for (int i = 0; i < 4; i++)
        t[ty + i * 8][tx] = W[(size_t)(k0 + ty + i * 8) * HIDD + n0 + tx];
    __syncthreads();
    #pragma unroll
    for (int i = 0; i < 4; i++) {
        float x = t[tx][ty + i * 8];
        __nv_bfloat16 h = __float2bfloat16(x);
        __nv_bfloat16 l = __float2bfloat16(x - __bfloat162float(h));
        size_t o = (size_t)(n0 + ty + i * 8) * HIDD + k0 + tx;
        Th[o] = h;
        Tl[o] = l;
    }
}

// ---------------------------------------------------------------------------
// HMMA 3x-emulated GEMM: CTA tile 128(M) x 64(N), K-chunk 32,
// 2-stage ring, target 3 CTAs/SM. Warp tile 32x32 (8 warps, 4m x 2n).
// ---------------------------------------------------------------------------
#define TPAD 40
// byte offsets within a stage
#define GA_L 10240                 // 128*40*2
#define GB_H 20480
#define GB_L 25600                 // +64*40*2
#define GSTG 30720                 // stage bytes
#define GSMEM (2 * GSTG)           // 61440
#define NCHUNK (HIDD / 32)         // 32

__global__ __launch_bounds__(256, 3) void mma_gemm_kernel(
    const __nv_bfloat16* __restrict__ AhiB, const __nv_bfloat16* __restrict__ AloB,
    const __nv_bfloat16* __restrict__ BthB, const __nv_bfloat16* __restrict__ BtlB,
    const float* __restrict__ b0, const float* __restrict__ b1,
    const float* __restrict__ b2,
    float* __restrict__ Cf, __nv_bfloat16* __restrict__ ChiB,
    __nv_bfloat16* __restrict__ CloB, int mode, float scaleQ)
{
    extern __shared__ __nv_bfloat16 sm[];
    const uint32_t smb = smem_u32(sm);

    const int tid  = threadIdx.x;
    const int wid  = tid >> 5, lane = tid & 31;
    const int z    = blockIdx.z;
    const int m0   = blockIdx.y * 128, n0 = blockIdx.x * 64;
    const int wm   = (wid >> 1) * 32;
    const int wn   = (wid & 1) * 32;

    const __nv_bfloat16* Ahi = AhiB + (size_t)z * MH;
    const __nv_bfloat16* Alo = AloB + (size_t)z * MH;
    const __nv_bfloat16* Bth = BthB + (size_t)z * HH;
    const __nv_bfloat16* Btl = BtlB + (size_t)z * HH;
    const float* bias = (z == 0) ? b0 : (z == 1) ? b1 : b2;
    const float scale = (z == 0) ? scaleQ : 1.0f;

    // A staging: 2 threads/row, 16 elems each; B staging: 4 threads/row, 8 elems
    const int arow = tid >> 1, acolE = (tid & 1) * 16;
    const int brow = tid >> 2, bcolE = (tid & 3) * 8;
    const size_t gA = (size_t)(m0 + arow) * HIDD + acolE;
    const size_t gB = (size_t)(n0 + brow) * HIDD + bcolE;
    const uint32_t sA = smb + (uint32_t)(arow * TPAD + acolE) * 2;
    const uint32_t sB = smb + GB_H + (uint32_t)(brow * TPAD + bcolE) * 2;

    float acc[2][4][4];
    #pragma unroll
    for (int im = 0; im < 2; im++)
        #pragma unroll
        for (int in = 0; in < 4; in++)
            #pragma unroll
            for (int j = 0; j < 4; j++) acc[im][in][j] = 0.f;

    const uint32_t aOff = (uint32_t)((wm + (lane & 15)) * TPAD +
                                     ((lane >> 4) << 3)) * 2;
    const uint32_t bOff = (uint32_t)((wn + (lane & 7) + ((lane & 16) ? 8 : 0)) * TPAD +
                                     ((lane & 8) ? 8 : 0)) * 2;

    auto issue = [&](int kc) {
        uint32_t st = (uint32_t)(kc & 1) * GSTG;
        size_t ga = gA + (size_t)kc * 32, gb = gB + (size_t)kc * 32;
        cp16(sA + st,          Ahi + ga); cp16(sA + st + 16,          Ahi + ga + 8);
        cp16(sA + st + GA_L,   Alo + ga); cp16(sA + st + GA_L + 16,   Alo + ga + 8);
        cp16(sB + st,          Bth + gb);
        cp16(sB + st + (GB_L - GB_H), Btl + gb);
        cp_commit();
    };
    issue(0);

    for (int kc = 0; kc < NCHUNK; kc++) {
        cp_wait0();
        __syncthreads();
        if (kc + 1 < NCHUNK) issue(kc + 1);

        const uint32_t st = smb + (uint32_t)(kc & 1) * GSTG;
        #pragma unroll
        for (int ks = 0; ks < 32; ks += 16) {
            uint32_t aH[2][4], aL[2][4];
            #pragma unroll
            for (int im = 0; im < 2; im++) {
                ldm4(aH[im], st + aOff + (uint32_t)(im * 16 * TPAD + ks) * 2);
                ldm4(aL[im], st + GA_L + aOff + (uint32_t)(im * 16 * TPAD + ks) * 2);
            }
            #pragma unroll
            for (int ib = 0; ib < 2; ib++) {
                uint32_t rh[4], rl[4];
                ldm4(rh, st + GB_H + bOff + (uint32_t)(ib * 16 * TPAD + ks) * 2);
                ldm4(rl, st + GB_L + bOff + (uint32_t)(ib * 16 * TPAD + ks) * 2);
                uint32_t bh0[2] = {rh[0], rh[1]}, bh1[2] = {rh[2], rh[3]};
                uint32_t bl0[2] = {rl[0], rl[1]}, bl1[2] = {rl[2], rl[3]};
                #pragma unroll
                for (int im = 0; im < 2; im++) {
                    mma_bf16(acc[im][ib*2],   aH[im], bh0);
                    mma_bf16(acc[im][ib*2],   aL[im], bh0);
                    mma_bf16(acc[im][ib*2],   aH[im], bl0);
                    mma_bf16(acc[im][ib*2+1], aH[im], bh1);
                    mma_bf16(acc[im][ib*2+1], aL[im], bh1);
                    mma_bf16(acc[im][ib*2+1], aH[im], bl1);
                }
            }
        }
    }

    const int er = lane >> 2, ec = (lane & 3) * 2;
    if (mode == 0) {
        #pragma unroll
        for (int im = 0; im < 2; im++)
            #pragma unroll
            for (int in = 0; in < 4; in++) {
                const int n = n0 + wn + in * 8 + ec;
                const float bx = bias[n], by = bias[n + 1];
                const int mA = m0 + wm + im * 16 + er;
                float2 v0 = {acc[im][in][0] + bx, acc[im][in][1] + by};
                *reinterpret_cast<float2*>(Cf + (size_t)mA * HIDD + n) = v0;
                float2 v1 = {acc[im][in][2] + bx, acc[im][in][3] + by};
                *reinterpret_cast<float2*>(Cf + (size_t)(mA + 8) * HIDD + n) = v1;
            }
    } else {
        uint32_t* chiu = reinterpret_cast<uint32_t*>(ChiB + (size_t)z * MH);
        uint32_t* clou = reinterpret_cast<uint32_t*>(CloB + (size_t)z * MH);
        #pragma unroll
        for (int im = 0; im < 2; im++)
            #pragma unroll
            for (int in = 0; in < 4; in++) {
                const int n = n0 + wn + in * 8 + ec;
                const float bx = bias[n], by = bias[n + 1];
                const int mA = m0 + wm + im * 16 + er;
                float f0 = (acc[im][in][0] + bx) * scale;
                float f1 = (acc[im][in][1] + by) * scale;
                float f2 = (acc[im][in][2] + bx) * scale;
                float f3 = (acc[im][in][3] + by) * scale;
                size_t i0 = ((size_t)mA * HIDD + n) >> 1;
                size_t i1 = ((size_t)(mA + 8) * HIDD + n) >> 1;
                uint32_t h01 = cvt2bf(f0, f1), h23 = cvt2bf(f2, f3);
                chiu[i0] = h01;
                chiu[i1] = h23;
                clou[i0] = cvt2bf(f0 - bflo_f(h01), f1 - bfhi_f(h01));
                clou[i1] = cvt2bf(f2 - bflo_f(h23), f3 - bfhi_f(h23));
            }
    }
}

// ---------------------------------------------------------------------------
// HMMA flash attention: 2-stage KV ring, 2 CTAs/SM, single barrier per tile,
// cvt-based packs, ballot-gated O rescale.
// ---------------------------------------------------------------------------
#define APAD 72
#define SQ_H 0
#define SQ_L (128 * APAD)
#define SKV  (2 * 128 * APAD)
#define KVS_K_L (64 * APAD)
#define KVS_V_H (2 * 64 * APAD)
#define KVS_V_L (3 * 64 * APAD)
#define KV_STG (4 * 64 * APAD)
#define ASMEM_E (SKV + 2 * KV_STG)
#define ASMEM_B (ASMEM_E * 2)              // 110592 bytes
#define TKV (SS / 64)                      // 32

__global__ __launch_bounds__(256, 2) void attn_mma_kernel(
    const __nv_bfloat16* __restrict__ phi, const __nv_bfloat16* __restrict__ plo,
    __nv_bfloat16* __restrict__ chi, __nv_bfloat16* __restrict__ clo)
{
    extern __shared__ __nv_bfloat16 sm[];
    const uint32_t smb = smem_u32(sm);

    const int tid  = threadIdx.x;
    const int wid  = tid >> 5, lane = tid & 31;
    const int b    = blockIdx.y >> 4;
    const int h    = blockIdx.y & 15;
    const int q0   = blockIdx.x * 128;
    const int hoff = h * HDD;

    const __nv_bfloat16* qhi = phi;
    const __nv_bfloat16* qlo = plo;
    const __nv_bfloat16* khi = phi + MH;
    const __nv_bfloat16* klo = plo + MH;
    const __nv_bfloat16* vhi = phi + 2 * MH;
    const __nv_bfloat16* vlo = plo + 2 * MH;

    // ---- Q tile (own commit group; first wait0 covers it)
    {
        const size_t qg = ((size_t)b * SS + q0) * HIDD + hoff;
        #pragma unroll
        for (int i = 0; i < 4; i++) {
            int idx = tid + i * 256;
            int r = idx >> 3, ch = idx & 7;
            cp16(smb + (uint32_t)(SQ_H + r * APAD + ch * 8) * 2,
                 qhi + qg + (size_t)r * HIDD + ch * 8);
            cp16(smb + (uint32_t)(SQ_L + r * APAD + ch * 8) * 2,
                 qlo + qg + (size_t)r * HIDD + ch * 8);
        }
        cp_commit();
    }

    auto issue_kv = [&](int kt) {
        const uint32_t sb = smb + (uint32_t)(SKV + (kt & 1) * KV_STG) * 2;
        #pragma unroll
        for (int i = 0; i < 2; i++) {
            int idx = tid + i * 256;
            int r = idx >> 3, ch = idx & 7;
            size_t g = ((size_t)b * SS + kt * 64 + r) * HIDD + hoff + ch * 8;
            uint32_t so = sb + (uint32_t)(r * APAD + ch * 8) * 2;
            cp16(so,                           khi + g);
            cp16(so + (uint32_t)KVS_K_L * 2,   klo + g);
            cp16(so + (uint32_t)KVS_V_H * 2,   vhi + g);
            cp16(so + (uint32_t)KVS_V_L * 2,   vlo + g);
        }
        cp_commit();
    };
    issue_kv(0);

    const uint32_t aRowOff = (uint32_t)((wid * 16 + (lane & 15)) * APAD +
                                        ((lane >> 4) << 3)) * 2;
    const uint32_t bRowOff = (uint32_t)(((lane & 7) + ((lane & 16) ? 8 : 0)) * APAD +
                                        ((lane & 8) ? 8 : 0)) * 2;
    const uint32_t vRowOff = (uint32_t)((lane & 15) * APAD +
                                        ((lane >> 4) << 3)) * 2;

    float O[8][4];
    #pragma unroll
    for (int j = 0; j < 8; j++)
        #pragma unroll
        for (int t = 0; t < 4; t++) O[j][t] = 0.f;
    float m0 = -1e30f, m1 = -1e30f, l0 = 0.f, l1 = 0.f;

    for (int kt = 0; kt < TKV; kt++) {
        cp_wait0();
        __syncthreads();        // copies visible AND prev-tile readers done
        if (kt + 1 < TKV) issue_kv(kt + 1);

        const uint32_t kvb = smb + (uint32_t)(SKV + (kt & 1) * KV_STG) * 2;

        // ---- S = Q K^T (3-term; Q frags reloaded per tile)
        float sf[8][4];
        #pragma unroll
        for (int j = 0; j < 8; j++)
            #pragma unroll
            for (int t = 0; t < 4; t++) sf[j][t] = 0.f;

        #pragma unroll
        for (int kk = 0; kk < 4; kk++) {
            uint32_t qh[4], ql[4];
            ldm4(qh, smb + (uint32_t)SQ_H * 2 + aRowOff + kk * 32);
            ldm4(ql, smb + (uint32_t)SQ_L * 2 + aRowOff + kk * 32);
            #pragma unroll
            for (int nb = 0; nb < 4; nb++) {
                uint32_t rh[4], rl[4];
                ldm4(rh, kvb + bRowOff + (uint32_t)(nb * 16 * APAD) * 2 + kk * 32);
                ldm4(rl, kvb + (uint32_t)KVS_K_L * 2 + bRowOff +
                          (uint32_t)(nb * 16 * APAD) * 2 + kk * 32);
                uint32_t bh0[2] = {rh[0], rh[1]}, bh1[2] = {rh[2], rh[3]};
                uint32_t bl0[2] = {rl[0], rl[1]}, bl1[2] = {rl[2], rl[3]};
                mma_bf16(sf[nb*2],   qh, bh0);
                mma_bf16(sf[nb*2],   ql, bh0);
                mma_bf16(sf[nb*2],   qh, bl0);
                mma_bf16(sf[nb*2+1], qh, bh1);
                mma_bf16(sf[nb*2+1], ql, bh1);
                mma_bf16(sf[nb*2+1], qh, bl1);
            }
        }

        // ---- online softmax (exp2 domain)
        float mx0 = -1e30f, mx1 = -1e30f;
        #pragma unroll
        for (int j = 0; j < 8; j++) {
            mx0 = fmaxf(mx0, fmaxf(sf[j][0], sf[j][1]));
            mx1 = fmaxf(mx1, fmaxf(sf[j][2], sf[j][3]));
        }
        mx0 = fmaxf(mx0, __shfl_xor_sync(0xffffffffu, mx0, 1));
        mx0 = fmaxf(mx0, __shfl_xor_sync(0xffffffffu, mx0, 2));
        mx1 = fmaxf(mx1, __shfl_xor_sync(0xffffffffu, mx1, 1));
        mx1 = fmaxf(mx1, __shfl_xor_sync(0xffffffffu, mx1, 2));
        float mn0 = fmaxf(m0, mx0), mn1 = fmaxf(m1, mx1);
        float c0 = exp2f(m0 - mn0), c1 = exp2f(m1 - mn1);
        m0 = mn0; m1 = mn1;

        float rs0 = 0.f, rs1 = 0.f;
        #pragma unroll
        for (int j = 0; j < 8; j++) {
            sf[j][0] = exp2f(sf[j][0] - mn0);
            sf[j][1] = exp2f(sf[j][1] - mn0);
            sf[j][2] = exp2f(sf[j][2] - mn1);
            sf[j][3] = exp2f(sf[j][3] - mn1);
            rs0 += sf[j][0] + sf[j][1];
            rs1 += sf[j][2] + sf[j][3];
        }
        rs0 += __shfl_xor_sync(0xffffffffu, rs0, 1);
        rs0 += __shfl_xor_sync(0xffffffffu, rs0, 2);
        rs1 += __shfl_xor_sync(0xffffffffu, rs1, 1);
        rs1 += __shfl_xor_sync(0xffffffffu, rs1, 2);
        l0 = l0 * c0 + rs0;
        l1 = l1 * c1 + rs1;

        // ---- rescale O only if some lane's max changed (exact skip)
        if (__any_sync(0xffffffffu, (c0 < 1.f) || (c1 < 1.f))) {
            #pragma unroll
            for (int j = 0; j < 8; j++) {
                O[j][0] *= c0; O[j][1] *= c0;
                O[j][2] *= c1; O[j][3] *= c1;
            }
        }

        // ---- pack P hi/lo into A fragments (cvt.bf16x2-based)
        uint32_t ph01[8], ph23[8], pl01[8], pl23[8];
        #pragma unroll
        for (int j = 0; j < 8; j++) {
            uint32_t h01 = cvt2bf(sf[j][0], sf[j][1]);
            uint32_t h23 = cvt2bf(sf[j][2], sf[j][3]);
            ph01[j] = h01;
            ph23[j] = h23;
            pl01[j] = cvt2bf(sf[j][0] - bflo_f(h01), sf[j][1] - bfhi_f(h01));
            pl23[j] = cvt2bf(sf[j][2] - bflo_f(h23), sf[j][3] - bfhi_f(h23));
        }

        // ---- O += P V (3-term), V via ldmatrix.trans
        #pragma unroll
        for (int kk = 0; kk < 4; kk++) {
            uint32_t ah[4] = {ph01[2*kk], ph23[2*kk], ph01[2*kk+1], ph23[2*kk+1]};
            uint32_t al[4] = {pl01[2*kk], pl23[2*kk], pl01[2*kk+1], pl23[2*kk+1]};
            #pragma unroll
            for (int nb = 0; nb < 4; nb++) {
                uint32_t rh[4], rl[4];
                uint32_t voff = vRowOff + (uint32_t)(kk * 16 * APAD + nb * 16) * 2;
                ldm4t(rh, kvb + (uint32_t)KVS_V_H * 2 + voff);
                ldm4t(rl, kvb + (uint32_t)KVS_V_L * 2 + voff);
                uint32_t bh0[2] = {rh[0], rh[1]}, bh1[2] = {rh[2], rh[3]};
                uint32_t bl0[2] = {rl[0], rl[1]}, bl1[2] = {rl[2], rl[3]};
                mma_bf16(O[nb*2],   ah, bh0);
                mma_bf16(O[nb*2],   al, bh0);
                mma_bf16(O[nb*2],   ah, bl0);
                mma_bf16(O[nb*2+1], ah, bh1);
                mma_bf16(O[nb*2+1], al, bh1);
                mma_bf16(O[nb*2+1], ah, bl1);
            }
        }
        // no end-of-loop barrier: next iteration's top barrier orders
        // stage overwrite (distance-1 issue) against this tile's readers
    }

    // ---- epilogue: ctx hi/lo (cvt-based)
    const int er = lane >> 2, ec = (lane & 3) * 2;
    const float inv0 = 1.f / l0, inv1 = 1.f / l1;
    const int row0 = q0 + wid * 16 + er;
    uint32_t* chiu = reinterpret_cast<uint32_t*>(chi);
    uint32_t* clou = reinterpret_cast<uint32_t*>(clo);
    #pragma unroll
    for (int j = 0; j < 8; j++) {
        const int col = hoff + j * 8 + ec;
        float f0 = O[j][0] * inv0, f1 = O[j][1] * inv0;
        float f2 = O[j][2] * inv1, f3 = O[j][3] * inv1;
        size_t i0 = (((size_t)b * SS + row0) * HIDD + col) >> 1;
        size_t i1 = (((size_t)b * SS + row0 + 8) * HIDD + col) >> 1;
        uint32_t h01 = cvt2bf(f0, f1), h23 = cvt2bf(f2, f3);
        chiu[i0] = h01;
        chiu[i1] = h23;
        clou[i0] = cvt2bf(f0 - bflo_f(h01), f1 - bfhi_f(h01));
        clou[i1] = cvt2bf(f2 - bflo_f(h23), f3 - bfhi_f(h23));
    }
}

// ---------------------------------------------------------------------------

extern "C" void kernel_launch(void* const* d_in, const int* in_sizes, int n_in,
                              void* d_out, int out_size)
{
    const float* query = (const float*)d_in[0];
    const float* key_  = (const float*)d_in[1];
    const float* value = (const float*)d_in[2];
    const float* Wq    = (const float*)d_in[3];
    const float* bq    = (const float*)d_in[4];
    const float* Wk    = (const float*)d_in[5];
    const float* bk    = (const float*)d_in[6];
    const float* Wv    = (const float*)d_in[7];
    const float* bv    = (const float*)d_in[8];
    const float* Wo    = (const float*)d_in[9];
    const float* bo    = (const float*)d_in[10];
    float* out = (float*)d_out;

    __nv_bfloat16 *inhi, *inlo, *wthi, *wtlo, *phi, *plo, *chi, *clo;
    cudaGetSymbolAddress((void**)&inhi, g_inhi);
    cudaGetSymbolAddress((void**)&inlo, g_inlo);
    cudaGetSymbolAddress((void**)&wthi, g_wthi);
    cudaGetSymbolAddress((void**)&wtlo, g_wtlo);
    cudaGetSymbolAddress((void**)&phi, g_phi);
    cudaGetSymbolAddress((void**)&plo, g_plo);
    cudaGetSymbolAddress((void**)&chi, g_chi);
    cudaGetSymbolAddress((void**)&clo, g_clo);

    cudaFuncSetAttribute(mma_gemm_kernel,
                         cudaFuncAttributeMaxDynamicSharedMemorySize, GSMEM);
    cudaFuncSetAttribute(attn_mma_kernel,
                         cudaFuncAttributeMaxDynamicSharedMemorySize, ASMEM_B);

    const int n4 = (int)(MH / 4);
    const float qscale = 0.125f * 1.44269504088896f;  // 1/sqrt(HD) * log2(e)

    split3_kernel<<<dim3(n4 / 256, 3), 256>>>(query, key_, value, inhi, inlo, n4);
    splitT4_kernel<<<dim3(32, 32, 4), 256>>>(Wq, Wk, Wv, Wo, wthi, wtlo);

    // Q,K,V projections (grid.z = 3), N-tile 64
    mma_gemm_kernel<<<dim3(HIDD / 64, MM / 128, 3), 256, GSMEM>>>(
        inhi, inlo, wthi, wtlo, bq, bk, bv,
        nullptr, phi, plo, 1, qscale);

    attn_mma_kernel<<<dim3(SS / 128, BB * NHH), 256, ASMEM_B>>>(phi, plo, chi, clo);

    // output projection (weight slot 3, fp32 out)
    mma_gemm_kernel<<<dim3(HIDD / 64, MM / 128, 1), 256, GSMEM>>>(
        chi, clo, wthi + 3 * HH, wtlo + 3 * HH, bo, bo, bo,
        out, nullptr, nullptr, 0, 1.0f);
}

// round 11
// speedup vs baseline: 1.0218x; 1.0218x over previous
#include <cuda_runtime.h>
#include <cuda_bf16.h>
#include <stdint.h>
#include <math.h>

#define BB   2
#define SS   2048
#define HIDD 1024
#define NHH  16
#define HDD  64
#define MM   (BB * SS)   // 4096 rows

static constexpr size_t MH = (size_t)MM * HIDD;
static constexpr size_t HH = (size_t)HIDD * HIDD;

// ---------------------------------------------------------------------------
// Scratch (bf16 hi/lo everywhere)
// ---------------------------------------------------------------------------
__device__ __nv_bfloat16 g_inhi[3 * MH];
__device__ __nv_bfloat16 g_inlo[3 * MH];
__device__ __nv_bfloat16 g_wthi[4 * HH];
__device__ __nv_bfloat16 g_wtlo[4 * HH];
__device__ __nv_bfloat16 g_phi[3 * MH];
__device__ __nv_bfloat16 g_plo[3 * MH];
__device__ __nv_bfloat16 g_chi[MH];
__device__ __nv_bfloat16 g_clo[MH];

// ---------------------------------------------------------------------------
// PTX helpers
// ---------------------------------------------------------------------------
__device__ __forceinline__ uint32_t smem_u32(const void* p) {
    uint32_t a;
    asm("{ .reg .u64 t; cvta.to.shared.u64 t, %1; cvt.u32.u64 %0, t; }"
        : "=r"(a) : "l"(p));
    return a;
}
__device__ __forceinline__ void cp16(uint32_t saddr, const void* g) {
    asm volatile("cp.async.cg.shared.global [%0], [%1], 16;"
                 :: "r"(saddr), "l"(g) : "memory");
}
__device__ __forceinline__ void cp_commit() {
    asm volatile("cp.async.commit_group;" ::: "memory");
}
__device__ __forceinline__ void cp_wait0() {
    asm volatile("cp.async.wait_group 0;" ::: "memory");
}
__device__ __forceinline__ void ldm4(uint32_t* r, uint32_t addr) {
    asm volatile("ldmatrix.sync.aligned.m8n8.x4.shared.b16 {%0,%1,%2,%3}, [%4];"
                 : "=r"(r[0]), "=r"(r[1]), "=r"(r[2]), "=r"(r[3]) : "r"(addr));
}
__device__ __forceinline__ void ldm4t(uint32_t* r, uint32_t addr) {
    asm volatile("ldmatrix.sync.aligned.m8n8.x4.trans.shared.b16 {%0,%1,%2,%3}, [%4];"
                 : "=r"(r[0]), "=r"(r[1]), "=r"(r[2]), "=r"(r[3]) : "r"(addr));
}
__device__ __forceinline__ void mma_bf16(float* c, const uint32_t* a,
                                         const uint32_t* b) {
    asm volatile(
        "mma.sync.aligned.m16n8k16.row.col.f32.bf16.bf16.f32 "
        "{%0,%1,%2,%3}, {%4,%5,%6,%7}, {%8,%9}, {%0,%1,%2,%3};"
        : "+f"(c[0]), "+f"(c[1]), "+f"(c[2]), "+f"(c[3])
        : "r"(a[0]), "r"(a[1]), "r"(a[2]), "r"(a[3]), "r"(b[0]), "r"(b[1]));
}
// pack two floats -> bf16x2 {lo=a, hi=b} in ONE cvt
__device__ __forceinline__ uint32_t cvt2bf(float a, float b) {
    uint32_t r;
    asm("cvt.rn.bf16x2.f32 %0, %1, %2;" : "=r"(r) : "f"(b), "f"(a));
    return r;
}
__device__ __forceinline__ float bflo_f(uint32_t p) {
    return __uint_as_float(p << 16);
}
__device__ __forceinline__ float bfhi_f(uint32_t p) {
    return __uint_as_float(p & 0xffff0000u);
}
// guaranteed-MUFU exp2
__device__ __forceinline__ float ex2(float x) {
    float r;
    asm("ex2.approx.ftz.f32 %0, %1;" : "=f"(r) : "f"(x));
    return r;
}

// ---------------------------------------------------------------------------
// Batched fp32 -> bf16 hi/lo split (3 inputs via grid.y)
// ---------------------------------------------------------------------------
__global__ __launch_bounds__(256) void split3_kernel(
    const float* __restrict__ x0, const float* __restrict__ x1,
    const float* __restrict__ x2, __nv_bfloat16* __restrict__ hiB,
    __nv_bfloat16* __restrict__ loB, int n4)
{
    int i = blockIdx.x * 256 + threadIdx.x;
    if (i >= n4) return;
    const int z = blockIdx.y;
    const float* x = (z == 0) ? x0 : (z == 1) ? x1 : x2;
    float4 v = reinterpret_cast<const float4*>(x)[i];
    uint2 ho, llo;
    ho.x  = cvt2bf(v.x, v.y);
    ho.y  = cvt2bf(v.z, v.w);
    llo.x = cvt2bf(v.x - bflo_f(ho.x), v.y - bfhi_f(ho.x));
    llo.y = cvt2bf(v.z - bflo_f(ho.y), v.w - bfhi_f(ho.y));
    size_t base = (size_t)z * (MH / 4);
    reinterpret_cast<uint2*>(hiB)[base + i] = ho;
    reinterpret_cast<uint2*>(loB)[base + i] = llo;
}

// ---------------------------------------------------------------------------
// Batched W [K][N] fp32 -> W^T [N][K] bf16 hi/lo (4 weights via grid.z)
// ---------------------------------------------------------------------------
__global__ __launch_bounds__(256) void splitT4_kernel(
    const float* __restrict__ W0, const float* __restrict__ W1,
    const float* __restrict__ W2, const float* __restrict__ W3,
    __nv_bfloat16* __restrict__ ThB, __nv_bfloat16* __restrict__ TlB)
{
    __shared__ float t[32][33];
    const int z = blockIdx.z;
    const float* W = (z == 0) ? W0 : (z == 1) ? W1 : (z == 2) ? W2 : W3;
    __nv_bfloat16* Th = ThB + (size_t)z * HH;
    __nv_bfloat16* Tl = TlB + (size_t)z * HH;
    int n0 = blockIdx.x * 32, k0 = blockIdx.y * 32;
    int tx = threadIdx.x & 31, ty = threadIdx.x >> 5;
    #pragma unroll
    for (int i = 0; i < 4; i++)
        t[ty + i * 8][tx] = W[(size_t)(k0 + ty + i * 8) * HIDD + n0 + tx];
    __syncthreads();
    #pragma unroll
    for (int i = 0; i < 4; i++) {
        float x = t[tx][ty + i * 8];
        __nv_bfloat16 h = __float2bfloat16(x);
        __nv_bfloat16 l = __float2bfloat16(x - __bfloat162float(h));
        size_t o = (size_t)(n0 + ty + i * 8) * HIDD + k0 + tx;
        Th[o] = h;
        Tl[o] = l;
    }
}

// ---------------------------------------------------------------------------
// HMMA 3x-emulated GEMM: CTA tile 128x128, K-chunk 32, 2-stage ring,
// 2 CTAs/SM, interleaved MMA ordering (acc reuse distance 4).
// ---------------------------------------------------------------------------
#define TPAD 40
#define TILE_E (128 * TPAD)
#define TILE_B (TILE_E * 2)        // 10240
#define STAGE_B (4 * TILE_B)       // 40960
#define GSMEM (2 * STAGE_B)        // 81920
#define NCHUNK (HIDD / 32)         // 32

__global__ __launch_bounds__(256, 2) void mma_gemm_kernel(
    const __nv_bfloat16* __restrict__ AhiB, const __nv_bfloat16* __restrict__ AloB,
    const __nv_bfloat16* __restrict__ BthB, const __nv_bfloat16* __restrict__ BtlB,
    const float* __restrict__ b0, const float* __restrict__ b1,
    const float* __restrict__ b2,
    float* __restrict__ Cf, __nv_bfloat16* __restrict__ ChiB,
    __nv_bfloat16* __restrict__ CloB, int mode, float scaleQ)
{
    extern __shared__ __nv_bfloat16 sm[];
    const uint32_t smb = smem_u32(sm);

    const int tid  = threadIdx.x;
    const int wid  = tid >> 5, lane = tid & 31;
    const int z    = blockIdx.z;
    const int m0   = blockIdx.y * 128, n0 = blockIdx.x * 128;
    const int wm   = (wid >> 1) * 32;
    const int wn   = (wid & 1) * 64;

    const __nv_bfloat16* Ahi = AhiB + (size_t)z * MH;
    const __nv_bfloat16* Alo = AloB + (size_t)z * MH;
    const __nv_bfloat16* Bth = BthB + (size_t)z * HH;
    const __nv_bfloat16* Btl = BtlB + (size_t)z * HH;
    const float* bias = (z == 0) ? b0 : (z == 1) ? b1 : b2;
    const float scale = (z == 0) ? scaleQ : 1.0f;

    const int lrow = tid >> 1;
    const int lcol = (tid & 1) * 16;
    const size_t gA = (size_t)(m0 + lrow) * HIDD + lcol;
    const size_t gB = (size_t)(n0 + lrow) * HIDD + lcol;
    const uint32_t sO = smb + (uint32_t)(lrow * TPAD + lcol) * 2;

    float acc[2][8][4];
    #pragma unroll
    for (int im = 0; im < 2; im++)
        #pragma unroll
        for (int in = 0; in < 8; in++)
            #pragma unroll
            for (int j = 0; j < 4; j++) acc[im][in][j] = 0.f;

    const uint32_t aOff = (uint32_t)((wm + (lane & 15)) * TPAD +
                                     ((lane >> 4) << 3)) * 2;
    const uint32_t bOff = (uint32_t)((wn + (lane & 7) + ((lane & 16) ? 8 : 0)) * TPAD +
                                     ((lane & 8) ? 8 : 0)) * 2;

    auto issue = [&](int kc) {
        uint32_t so = sO + (uint32_t)(kc & 1) * STAGE_B;
        size_t ga = gA + (size_t)kc * 32, gb = gB + (size_t)kc * 32;
        cp16(so,              Ahi + ga); cp16(so + 16,              Ahi + ga + 8);
        cp16(so + TILE_B,     Alo + ga); cp16(so + TILE_B + 16,     Alo + ga + 8);
        cp16(so + 2*TILE_B,   Bth + gb); cp16(so + 2*TILE_B + 16,   Bth + gb + 8);
        cp16(so + 3*TILE_B,   Btl + gb); cp16(so + 3*TILE_B + 16,   Btl + gb + 8);
        cp_commit();
    };
    issue(0);

    for (int kc = 0; kc < NCHUNK; kc++) {
        cp_wait0();
        __syncthreads();
        if (kc + 1 < NCHUNK) issue(kc + 1);

        const uint32_t st = smb + (uint32_t)(kc & 1) * STAGE_B;
        #pragma unroll
        for (int ks = 0; ks < 32; ks += 16) {
            uint32_t aH[2][4], aL[2][4];
            #pragma unroll
            for (int im = 0; im < 2; im++) {
                ldm4(aH[im], st + aOff + (uint32_t)(im * 16 * TPAD + ks) * 2);
                ldm4(aL[im], st + TILE_B + aOff + (uint32_t)(im * 16 * TPAD + ks) * 2);
            }
            #pragma unroll
            for (int ib = 0; ib < 4; ib++) {
                uint32_t rh[4], rl[4];
                ldm4(rh, st + 2*TILE_B + bOff + (uint32_t)(ib * 16 * TPAD + ks) * 2);
                ldm4(rl, st + 3*TILE_B + bOff + (uint32_t)(ib * 16 * TPAD + ks) * 2);
                uint32_t bh0[2] = {rh[0], rh[1]}, bh1[2] = {rh[2], rh[3]};
                uint32_t bl0[2] = {rl[0], rl[1]}, bl1[2] = {rl[2], rl[3]};
                // term-major, acc reuse distance 4
                mma_bf16(acc[0][ib*2],   aH[0], bh0);
                mma_bf16(acc[0][ib*2+1], aH[0], bh1);
                mma_bf16(acc[1][ib*2],   aH[1], bh0);
                mma_bf16(acc[1][ib*2+1], aH[1], bh1);
                mma_bf16(acc[0][ib*2],   aL[0], bh0);
                mma_bf16(acc[0][ib*2+1], aL[0], bh1);
                mma_bf16(acc[1][ib*2],   aL[1], bh0);
                mma_bf16(acc[1][ib*2+1], aL[1], bh1);
                mma_bf16(acc[0][ib*2],   aH[0], bl0);
                mma_bf16(acc[0][ib*2+1], aH[0], bl1);
                mma_bf16(acc[1][ib*2],   aH[1], bl0);
                mma_bf16(acc[1][ib*2+1], aH[1], bl1);
            }
        }
    }

    const int er = lane >> 2, ec = (lane & 3) * 2;
    if (mode == 0) {
        #pragma unroll
        for (int im = 0; im < 2; im++)
            #pragma unroll
            for (int in = 0; in < 8; in++) {
                const int n = n0 + wn + in * 8 + ec;
                const float bx = bias[n], by = bias[n + 1];
                const int mA = m0 + wm + im * 16 + er;
                float2 v0 = {acc[im][in][0] + bx, acc[im][in][1] + by};
                *reinterpret_cast<float2*>(Cf + (size_t)mA * HIDD + n) = v0;
                float2 v1 = {acc[im][in][2] + bx, acc[im][in][3] + by};
                *reinterpret_cast<float2*>(Cf + (size_t)(mA + 8) * HIDD + n) = v1;
            }
    } else {
        uint32_t* chiu = reinterpret_cast<uint32_t*>(ChiB + (size_t)z * MH);
        uint32_t* clou = reinterpret_cast<uint32_t*>(CloB + (size_t)z * MH);
        #pragma unroll
        for (int im = 0; im < 2; im++)
            #pragma unroll
            for (int in = 0; in < 8; in++) {
                const int n = n0 + wn + in * 8 + ec;
                const float bx = bias[n], by = bias[n + 1];
                const int mA = m0 + wm + im * 16 + er;
                float f0 = (acc[im][in][0] + bx) * scale;
                float f1 = (acc[im][in][1] + by) * scale;
                float f2 = (acc[im][in][2] + bx) * scale;
                float f3 = (acc[im][in][3] + by) * scale;
                size_t i0 = ((size_t)mA * HIDD + n) >> 1;
                size_t i1 = ((size_t)(mA + 8) * HIDD + n) >> 1;
                uint32_t h01 = cvt2bf(f0, f1), h23 = cvt2bf(f2, f3);
                chiu[i0] = h01;
                chiu[i1] = h23;
                clou[i0] = cvt2bf(f0 - bflo_f(h01), f1 - bfhi_f(h01));
                clou[i1] = cvt2bf(f2 - bflo_f(h23), f3 - bfhi_f(h23));
            }
    }
}

// ---------------------------------------------------------------------------
// HMMA flash attention: 2-stage KV ring, 2 CTAs/SM, ex2-MUFU softmax,
// interleaved MMA ordering (acc reuse distance 2).
// ---------------------------------------------------------------------------
#define APAD 72
#define SQ_H 0
#define SQ_L (128 * APAD)
#define SKV  (2 * 128 * APAD)
#define KVS_K_L (64 * APAD)
#define KVS_V_H (2 * 64 * APAD)
#define KVS_V_L (3 * 64 * APAD)
#define KV_STG (4 * 64 * APAD)
#define ASMEM_E (SKV + 2 * KV_STG)
#define ASMEM_B (ASMEM_E * 2)              // 110592 bytes
#define TKV (SS / 64)                      // 32

__global__ __launch_bounds__(256, 2) void attn_mma_kernel(
    const __nv_bfloat16* __restrict__ phi, const __nv_bfloat16* __restrict__ plo,
    __nv_bfloat16* __restrict__ chi, __nv_bfloat16* __restrict__ clo)
{
    extern __shared__ __nv_bfloat16 sm[];
    const uint32_t smb = smem_u32(sm);

    const int tid  = threadIdx.x;
    const int wid  = tid >> 5, lane = tid & 31;
    const int b    = blockIdx.y >> 4;
    const int h    = blockIdx.y & 15;
    const int q0   = blockIdx.x * 128;
    const int hoff = h * HDD;

    const __nv_bfloat16* qhi = phi;
    const __nv_bfloat16* qlo = plo;
    const __nv_bfloat16* khi = phi + MH;
    const __nv_bfloat16* klo = plo + MH;
    const __nv_bfloat16* vhi = phi + 2 * MH;
    const __nv_bfloat16* vlo = plo + 2 * MH;

    // ---- Q tile (own commit group; first wait0 covers it)
    {
        const size_t qg = ((size_t)b * SS + q0) * HIDD + hoff;
        #pragma unroll
        for (int i = 0; i < 4; i++) {
            int idx = tid + i * 256;
            int r = idx >> 3, ch = idx & 7;
            cp16(smb + (uint32_t)(SQ_H + r * APAD + ch * 8) * 2,
                 qhi + qg + (size_t)r * HIDD + ch * 8);
            cp16(smb + (uint32_t)(SQ_L + r * APAD + ch * 8) * 2,
                 qlo + qg + (size_t)r * HIDD + ch * 8);
        }
        cp_commit();
    }

    auto issue_kv = [&](int kt) {
        const uint32_t sb = smb + (uint32_t)(SKV + (kt & 1) * KV_STG) * 2;
        #pragma unroll
        for (int i = 0; i < 2; i++) {
            int idx = tid + i * 256;
            int r = idx >> 3, ch = idx & 7;
            size_t g = ((size_t)b * SS + kt * 64 + r) * HIDD + hoff + ch * 8;
            uint32_t so = sb + (uint32_t)(r * APAD + ch * 8) * 2;
            cp16(so,                           khi + g);
            cp16(so + (uint32_t)KVS_K_L * 2,   klo + g);
            cp16(so + (uint32_t)KVS_V_H * 2,   vhi + g);
            cp16(so + (uint32_t)KVS_V_L * 2,   vlo + g);
        }
        cp_commit();
    };
    issue_kv(0);

    const uint32_t aRowOff = (uint32_t)((wid * 16 + (lane & 15)) * APAD +
                                        ((lane >> 4) << 3)) * 2;
    const uint32_t bRowOff = (uint32_t)(((lane & 7) + ((lane & 16) ? 8 : 0)) * APAD +
                                        ((lane & 8) ? 8 : 0)) * 2;
    const uint32_t vRowOff = (uint32_t)((lane & 15) * APAD +
                                        ((lane >> 4) << 3)) * 2;

    float O[8][4];
    #pragma unroll
    for (int j = 0; j < 8; j++)
        #pragma unroll
        for (int t = 0; t < 4; t++) O[j][t] = 0.f;
    float m0 = -1e30f, m1 = -1e30f, l0 = 0.f, l1 = 0.f;

    for (int kt = 0; kt < TKV; kt++) {
        cp_wait0();
        __syncthreads();        // copies visible AND prev-tile readers done
        if (kt + 1 < TKV) issue_kv(kt + 1);

        const uint32_t kvb = smb + (uint32_t)(SKV + (kt & 1) * KV_STG) * 2;

        // ---- S = Q K^T (3-term; interleaved, acc distance 2)
        float sf[8][4];
        #pragma unroll
        for (int j = 0; j < 8; j++)
            #pragma unroll
            for (int t = 0; t < 4; t++) sf[j][t] = 0.f;

        #pragma unroll
        for (int kk = 0; kk < 4; kk++) {
            uint32_t qh[4], ql[4];
            ldm4(qh, smb + (uint32_t)SQ_H * 2 + aRowOff + kk * 32);
            ldm4(ql, smb + (uint32_t)SQ_L * 2 + aRowOff + kk * 32);
            #pragma unroll
            for (int nb = 0; nb < 4; nb++) {
                uint32_t rh[4], rl[4];
                ldm4(rh, kvb + bRowOff + (uint32_t)(nb * 16 * APAD) * 2 + kk * 32);
                ldm4(rl, kvb + (uint32_t)KVS_K_L * 2 + bRowOff +
                          (uint32_t)(nb * 16 * APAD) * 2 + kk * 32);
                uint32_t bh0[2] = {rh[0], rh[1]}, bh1[2] = {rh[2], rh[3]};
                uint32_t bl0[2] = {rl[0], rl[1]}, bl1[2] = {rl[2], rl[3]};
                mma_bf16(sf[nb*2],   qh, bh0);
                mma_bf16(sf[nb*2+1], qh, bh1);
                mma_bf16(sf[nb*2],   ql, bh0);
                mma_bf16(sf[nb*2+1], ql, bh1);
                mma_bf16(sf[nb*2],   qh, bl0);
                mma_bf16(sf[nb*2+1], qh, bl1);
            }
        }

        // ---- online softmax (exp2 domain, MUFU ex2)
        float mx0 = -1e30f, mx1 = -1e30f;
        #pragma unroll
        for (int j = 0; j < 8; j++) {
            mx0 = fmaxf(mx0, fmaxf(sf[j][0], sf[j][1]));
            mx1 = fmaxf(mx1, fmaxf(sf[j][2], sf[j][3]));
        }
        mx0 = fmaxf(mx0, __shfl_xor_sync(0xffffffffu, mx0, 1));
        mx0 = fmaxf(mx0, __shfl_xor_sync(0xffffffffu, mx0, 2));
        mx1 = fmaxf(mx1, __shfl_xor_sync(0xffffffffu, mx1, 1));
        mx1 = fmaxf(mx1, __shfl_xor_sync(0xffffffffu, mx1, 2));
        float mn0 = fmaxf(m0, mx0), mn1 = fmaxf(m1, mx1);
        float c0 = ex2(m0 - mn0), c1 = ex2(m1 - mn1);
        m0 = mn0; m1 = mn1;

        float rs0 = 0.f, rs1 = 0.f;
        #pragma unroll
        for (int j = 0; j < 8; j++) {
            sf[j][0] = ex2(sf[j][0] - mn0);
            sf[j][1] = ex2(sf[j][1] - mn0);
            sf[j][2] = ex2(sf[j][2] - mn1);
            sf[j][3] = ex2(sf[j][3] - mn1);
            rs0 += sf[j][0] + sf[j][1];
            rs1 += sf[j][2] + sf[j][3];
        }
        rs0 += __shfl_xor_sync(0xffffffffu, rs0, 1);
        rs0 += __shfl_xor_sync(0xffffffffu, rs0, 2);
        rs1 += __shfl_xor_sync(0xffffffffu, rs1, 1);
        rs1 += __shfl_xor_sync(0xffffffffu, rs1, 2);
        l0 = l0 * c0 + rs0;
        l1 = l1 * c1 + rs1;

        // ---- rescale O only if some lane's max changed (exact skip)
        if (__any_sync(0xffffffffu, (c0 < 1.f) || (c1 < 1.f))) {
            #pragma unroll
            for (int j = 0; j < 8; j++) {
                O[j][0] *= c0; O[j][1] *= c0;
                O[j][2] *= c1; O[j][3] *= c1;
            }
        }

        // ---- pack P hi/lo into A fragments (cvt.bf16x2-based)
        uint32_t ph01[8], ph23[8], pl01[8], pl23[8];
        #pragma unroll
        for (int j = 0; j < 8; j++) {
            uint32_t h01 = cvt2bf(sf[j][0], sf[j][1]);
            uint32_t h23 = cvt2bf(sf[j][2], sf[j][3]);
            ph01[j] = h01;
            ph23[j] = h23;
            pl01[j] = cvt2bf(sf[j][0] - bflo_f(h01), sf[j][1] - bfhi_f(h01));
            pl23[j] = cvt2bf(sf[j][2] - bflo_f(h23), sf[j][3] - bfhi_f(h23));
        }

        // ---- O += P V (3-term, interleaved), V via ldmatrix.trans
        #pragma unroll
        for (int kk = 0; kk < 4; kk++) {
            uint32_t ah[4] = {ph01[2*kk], ph23[2*kk], ph01[2*kk+1], ph23[2*kk+1]};
            uint32_t al[4] = {pl01[2*kk], pl23[2*kk], pl01[2*kk+1], pl23[2*kk+1]};
            #pragma unroll
            for (int nb = 0; nb < 4; nb++) {
                uint32_t rh[4], rl[4];
                uint32_t voff = vRowOff + (uint32_t)(kk * 16 * APAD + nb * 16) * 2;
                ldm4t(rh, kvb + (uint32_t)KVS_V_H * 2 + voff);
                ldm4t(rl, kvb + (uint32_t)KVS_V_L * 2 + voff);
                uint32_t bh0[2] = {rh[0], rh[1]}, bh1[2] = {rh[2], rh[3]};
                uint32_t bl0[2] = {rl[0], rl[1]}, bl1[2] = {rl[2], rl[3]};
                mma_bf16(O[nb*2],   ah, bh0);
                mma_bf16(O[nb*2+1], ah, bh1);
                mma_bf16(O[nb*2],   al, bh0);
                mma_bf16(O[nb*2+1], al, bh1);
                mma_bf16(O[nb*2],   ah, bl0);
                mma_bf16(O[nb*2+1], ah, bl1);
            }
        }
        // no end-of-loop barrier: next iteration's top barrier orders
        // stage overwrite (distance-1 issue) against this tile's readers
    }

    // ---- epilogue: ctx hi/lo (cvt-based)
    const int er = lane >> 2, ec = (lane & 3) * 2;
    const float inv0 = 1.f / l0, inv1 = 1.f / l1;
    const int row0 = q0 + wid * 16 + er;
    uint32_t* chiu = reinterpret_cast<uint32_t*>(chi);
    uint32_t* clou = reinterpret_cast<uint32_t*>(clo);
    #pragma unroll
    for (int j = 0; j < 8; j++) {
        const int col = hoff + j * 8 + ec;
        float f0 = O[j][0] * inv0, f1 = O[j][1] * inv0;
        float f2 = O[j][2] * inv1, f3 = O[j][3] * inv1;
        size_t i0 = (((size_t)b * SS + row0) * HIDD + col) >> 1;
        size_t i1 = (((size_t)b * SS + row0 + 8) * HIDD + col) >> 1;
        uint32_t h01 = cvt2bf(f0, f1), h23 = cvt2bf(f2, f3);
        chiu[i0] = h01;
        chiu[i1] = h23;
        clou[i0] = cvt2bf(f0 - bflo_f(h01), f1 - bfhi_f(h01));
        clou[i1] = cvt2bf(f2 - bflo_f(h23), f3 - bfhi_f(h23));
    }
}

// ---------------------------------------------------------------------------

extern "C" void kernel_launch(void* const* d_in, const int* in_sizes, int n_in,
                              void* d_out, int out_size)
{
    const float* query = (const float*)d_in[0];
    const float* key_  = (const float*)d_in[1];
    const float* value = (const float*)d_in[2];
    const float* Wq    = (const float*)d_in[3];
    const float* bq    = (const float*)d_in[4];
    const float* Wk    = (const float*)d_in[5];
    const float* bk    = (const float*)d_in[6];
    const float* Wv    = (const float*)d_in[7];
    const float* bv    = (const float*)d_in[8];
    const float* Wo    = (const float*)d_in[9];
    const float* bo    = (const float*)d_in[10];
    float* out = (float*)d_out;

    __nv_bfloat16 *inhi, *inlo, *wthi, *wtlo, *phi, *plo, *chi, *clo;
    cudaGetSymbolAddress((void**)&inhi, g_inhi);
    cudaGetSymbolAddress((void**)&inlo, g_inlo);
    cudaGetSymbolAddress((void**)&wthi, g_wthi);
    cudaGetSymbolAddress((void**)&wtlo, g_wtlo);
    cudaGetSymbolAddress((void**)&phi, g_phi);
    cudaGetSymbolAddress((void**)&plo, g_plo);
    cudaGetSymbolAddress((void**)&chi, g_chi);
    cudaGetSymbolAddress((void**)&clo, g_clo);

    cudaFuncSetAttribute(mma_gemm_kernel,
                         cudaFuncAttributeMaxDynamicSharedMemorySize, GSMEM);
    cudaFuncSetAttribute(attn_mma_kernel,
                         cudaFuncAttributeMaxDynamicSharedMemorySize, ASMEM_B);

    const int n4 = (int)(MH / 4);
    const float qscale = 0.125f * 1.44269504088896f;  // 1/sqrt(HD) * log2(e)

    split3_kernel<<<dim3(n4 / 256, 3), 256>>>(query, key_, value, inhi, inlo, n4);
    splitT4_kernel<<<dim3(32, 32, 4), 256>>>(Wq, Wk, Wv, Wo, wthi, wtlo);

    // Q,K,V projections (grid.z = 3), 128x128 tiles
    mma_gemm_kernel<<<dim3(HIDD / 128, MM / 128, 3), 256, GSMEM>>>(
        inhi, inlo, wthi, wtlo, bq, bk, bv,
        nullptr, phi, plo, 1, qscale);

    attn_mma_kernel<<<dim3(SS / 128, BB * NHH), 256, ASMEM_B>>>(phi, plo, chi, clo);

    // output projection (weight slot 3, fp32 out)
    mma_gemm_kernel<<<dim3(HIDD / 128, MM / 128, 1), 256, GSMEM>>>(
        chi, clo, wthi + 3 * HH, wtlo + 3 * HH, bo, bo, bo,
        out, nullptr, nullptr, 0, 1.0f);
}

// round 12
// speedup vs baseline: 1.0293x; 1.0073x over previous
#include <cuda_runtime.h>
#include <cuda_bf16.h>
#include <stdint.h>
#include <math.h>

#define BB   2
#define SS   2048
#define HIDD 1024
#define NHH  16
#define HDD  64
#define MM   (BB * SS)   // 4096 rows

static constexpr size_t MH = (size_t)MM * HIDD;
static constexpr size_t HH = (size_t)HIDD * HIDD;

// ---------------------------------------------------------------------------
// Scratch (bf16 hi/lo everywhere)
// ---------------------------------------------------------------------------
__device__ __nv_bfloat16 g_inhi[3 * MH];
__device__ __nv_bfloat16 g_inlo[3 * MH];
__device__ __nv_bfloat16 g_wthi[4 * HH];
__device__ __nv_bfloat16 g_wtlo[4 * HH];
__device__ __nv_bfloat16 g_phi[3 * MH];
__device__ __nv_bfloat16 g_plo[3 * MH];
__device__ __nv_bfloat16 g_chi[MH];
__device__ __nv_bfloat16 g_clo[MH];

// ---------------------------------------------------------------------------
// PTX helpers
// ---------------------------------------------------------------------------
__device__ __forceinline__ uint32_t smem_u32(const void* p) {
    uint32_t a;
    asm("{ .reg .u64 t; cvta.to.shared.u64 t, %1; cvt.u32.u64 %0, t; }"
        : "=r"(a) : "l"(p));
    return a;
}
__device__ __forceinline__ void cp16(uint32_t saddr, const void* g) {
    asm volatile("cp.async.cg.shared.global [%0], [%1], 16;"
                 :: "r"(saddr), "l"(g) : "memory");
}
__device__ __forceinline__ void cp_commit() {
    asm volatile("cp.async.commit_group;" ::: "memory");
}
__device__ __forceinline__ void cp_wait0() {
    asm volatile("cp.async.wait_group 0;" ::: "memory");
}
__device__ __forceinline__ void ldm4(uint32_t* r, uint32_t addr) {
    asm volatile("ldmatrix.sync.aligned.m8n8.x4.shared.b16 {%0,%1,%2,%3}, [%4];"
                 : "=r"(r[0]), "=r"(r[1]), "=r"(r[2]), "=r"(r[3]) : "r"(addr));
}
__device__ __forceinline__ void ldm4t(uint32_t* r, uint32_t addr) {
    asm volatile("ldmatrix.sync.aligned.m8n8.x4.trans.shared.b16 {%0,%1,%2,%3}, [%4];"
                 : "=r"(r[0]), "=r"(r[1]), "=r"(r[2]), "=r"(r[3]) : "r"(addr));
}
__device__ __forceinline__ void mma_bf16(float* c, const uint32_t* a,
                                         const uint32_t* b) {
    asm volatile(
        "mma.sync.aligned.m16n8k16.row.col.f32.bf16.bf16.f32 "
        "{%0,%1,%2,%3}, {%4,%5,%6,%7}, {%8,%9}, {%0,%1,%2,%3};"
        : "+f"(c[0]), "+f"(c[1]), "+f"(c[2]), "+f"(c[3])
        : "r"(a[0]), "r"(a[1]), "r"(a[2]), "r"(a[3]), "r"(b[0]), "r"(b[1]));
}
// pack two floats -> bf16x2 {lo=a, hi=b} in ONE cvt
__device__ __forceinline__ uint32_t cvt2bf(float a, float b) {
    uint32_t r;
    asm("cvt.rn.bf16x2.f32 %0, %1, %2;" : "=r"(r) : "f"(b), "f"(a));
    return r;
}
__device__ __forceinline__ float bflo_f(uint32_t p) {
    return __uint_as_float(p << 16);
}
__device__ __forceinline__ float bfhi_f(uint32_t p) {
    return __uint_as_float(p & 0xffff0000u);
}
// guaranteed-MUFU exp2
__device__ __forceinline__ float ex2(float x) {
    float r;
    asm("ex2.approx.ftz.f32 %0, %1;" : "=f"(r) : "f"(x));
    return r;
}

// ---------------------------------------------------------------------------
// Batched fp32 -> bf16 hi/lo split (3 inputs via grid.y)
// ---------------------------------------------------------------------------
__global__ __launch_bounds__(256) void split3_kernel(
    const float* __restrict__ x0, const float* __restrict__ x1,
    const float* __restrict__ x2, __nv_bfloat16* __restrict__ hiB,
    __nv_bfloat16* __restrict__ loB, int n4)
{
    int i = blockIdx.x * 256 + threadIdx.x;
    if (i >= n4) return;
    const int z = blockIdx.y;
    const float* x = (z == 0) ? x0 : (z == 1) ? x1 : x2;
    float4 v = reinterpret_cast<const float4*>(x)[i];
    uint2 ho, llo;
    ho.x  = cvt2bf(v.x, v.y);
    ho.y  = cvt2bf(v.z, v.w);
    llo.x = cvt2bf(v.x - bflo_f(ho.x), v.y - bfhi_f(ho.x));
    llo.y = cvt2bf(v.z - bflo_f(ho.y), v.w - bfhi_f(ho.y));
    size_t base = (size_t)z * (MH / 4);
    reinterpret_cast<uint2*>(hiB)[base + i] = ho;
    reinterpret_cast<uint2*>(loB)[base + i] = llo;
}

// ---------------------------------------------------------------------------
// Batched W [K][N] fp32 -> W^T [N][K] bf16 hi/lo (4 weights via grid.z)
// ---------------------------------------------------------------------------
__global__ __launch_bounds__(256) void splitT4_kernel(
    const float* __restrict__ W0, const float* __restrict__ W1,
    const float* __restrict__ W2, const float* __restrict__ W3,
    __nv_bfloat16* __restrict__ ThB, __nv_bfloat16* __restrict__ TlB)
{
    __shared__ float t[32][33];
    const int z = blockIdx.z;
    const float* W = (z == 0) ? W0 : (z == 1) ? W1 : (z == 2) ? W2 : W3;
    __nv_bfloat16* Th = ThB + (size_t)z * HH;
    __nv_bfloat16* Tl = TlB + (size_t)z * HH;
    int n0 = blockIdx.x * 32, k0 = blockIdx.y * 32;
    int tx = threadIdx.x & 31, ty = threadIdx.x >> 5;
    #pragma unroll
    for (int i = 0; i < 4; i++)
        t[ty + i * 8][tx] = W[(size_t)(k0 + ty + i * 8) * HIDD + n0 + tx];
    __syncthreads();
    #pragma unroll
    for (int i = 0; i < 4; i++) {
        float x = t[tx][ty + i * 8];
        __nv_bfloat16 h = __float2bfloat16(x);
        __nv_bfloat16 l = __float2bfloat16(x - __bfloat162float(h));
        size_t o = (size_t)(n0 + ty + i * 8) * HIDD + k0 + tx;
        Th[o] = h;
        Tl[o] = l;
    }
}

// ---------------------------------------------------------------------------
// HMMA 3x-emulated GEMM: CTA tile 128x128, K-chunk 32, 2-stage ring,
// 2 CTAs/SM, interleaved MMA ordering (unchanged from round 11).
// ---------------------------------------------------------------------------
#define TPAD 40
#define TILE_E (128 * TPAD)
#define TILE_B (TILE_E * 2)        // 10240
#define STAGE_B (4 * TILE_B)       // 40960
#define GSMEM (2 * STAGE_B)        // 81920
#define NCHUNK (HIDD / 32)         // 32

__global__ __launch_bounds__(256, 2) void mma_gemm_kernel(
    const __nv_bfloat16* __restrict__ AhiB, const __nv_bfloat16* __restrict__ AloB,
    const __nv_bfloat16* __restrict__ BthB, const __nv_bfloat16* __restrict__ BtlB,
    const float* __restrict__ b0, const float* __restrict__ b1,
    const float* __restrict__ b2,
    float* __restrict__ Cf, __nv_bfloat16* __restrict__ ChiB,
    __nv_bfloat16* __restrict__ CloB, int mode, float scaleQ)
{
    extern __shared__ __nv_bfloat16 sm[];
    const uint32_t smb = smem_u32(sm);

    const int tid  = threadIdx.x;
    const int wid  = tid >> 5, lane = tid & 31;
    const int z    = blockIdx.z;
    const int m0   = blockIdx.y * 128, n0 = blockIdx.x * 128;
    const int wm   = (wid >> 1) * 32;
    const int wn   = (wid & 1) * 64;

    const __nv_bfloat16* Ahi = AhiB + (size_t)z * MH;
    const __nv_bfloat16* Alo = AloB + (size_t)z * MH;
    const __nv_bfloat16* Bth = BthB + (size_t)z * HH;
    const __nv_bfloat16* Btl = BtlB + (size_t)z * HH;
    const float* bias = (z == 0) ? b0 : (z == 1) ? b1 : b2;
    const float scale = (z == 0) ? scaleQ : 1.0f;

    const int lrow = tid >> 1;
    const int lcol = (tid & 1) * 16;
    const size_t gA = (size_t)(m0 + lrow) * HIDD + lcol;
    const size_t gB = (size_t)(n0 + lrow) * HIDD + lcol;
    const uint32_t sO = smb + (uint32_t)(lrow * TPAD + lcol) * 2;

    float acc[2][8][4];
    #pragma unroll
    for (int im = 0; im < 2; im++)
        #pragma unroll
        for (int in = 0; in < 8; in++)
            #pragma unroll
            for (int j = 0; j < 4; j++) acc[im][in][j] = 0.f;

    const uint32_t aOff = (uint32_t)((wm + (lane & 15)) * TPAD +
                                     ((lane >> 4) << 3)) * 2;
    const uint32_t bOff = (uint32_t)((wn + (lane & 7) + ((lane & 16) ? 8 : 0)) * TPAD +
                                     ((lane & 8) ? 8 : 0)) * 2;

    auto issue = [&](int kc) {
        uint32_t so = sO + (uint32_t)(kc & 1) * STAGE_B;
        size_t ga = gA + (size_t)kc * 32, gb = gB + (size_t)kc * 32;
        cp16(so,              Ahi + ga); cp16(so + 16,              Ahi + ga + 8);
        cp16(so + TILE_B,     Alo + ga); cp16(so + TILE_B + 16,     Alo + ga + 8);
        cp16(so + 2*TILE_B,   Bth + gb); cp16(so + 2*TILE_B + 16,   Bth + gb + 8);
        cp16(so + 3*TILE_B,   Btl + gb); cp16(so + 3*TILE_B + 16,   Btl + gb + 8);
        cp_commit();
    };
    issue(0);

    for (int kc = 0; kc < NCHUNK; kc++) {
        cp_wait0();
        __syncthreads();
        if (kc + 1 < NCHUNK) issue(kc + 1);

        const uint32_t st = smb + (uint32_t)(kc & 1) * STAGE_B;
        #pragma unroll
        for (int ks = 0; ks < 32; ks += 16) {
            uint32_t aH[2][4], aL[2][4];
            #pragma unroll
            for (int im = 0; im < 2; im++) {
                ldm4(aH[im], st + aOff + (uint32_t)(im * 16 * TPAD + ks) * 2);
                ldm4(aL[im], st + TILE_B + aOff + (uint32_t)(im * 16 * TPAD + ks) * 2);
            }
            #pragma unroll
            for (int ib = 0; ib < 4; ib++) {
                uint32_t rh[4], rl[4];
                ldm4(rh, st + 2*TILE_B + bOff + (uint32_t)(ib * 16 * TPAD + ks) * 2);
                ldm4(rl, st + 3*TILE_B + bOff + (uint32_t)(ib * 16 * TPAD + ks) * 2);
                uint32_t bh0[2] = {rh[0], rh[1]}, bh1[2] = {rh[2], rh[3]};
                uint32_t bl0[2] = {rl[0], rl[1]}, bl1[2] = {rl[2], rl[3]};
                mma_bf16(acc[0][ib*2],   aH[0], bh0);
                mma_bf16(acc[0][ib*2+1], aH[0], bh1);
                mma_bf16(acc[1][ib*2],   aH[1], bh0);
                mma_bf16(acc[1][ib*2+1], aH[1], bh1);
                mma_bf16(acc[0][ib*2],   aL[0], bh0);
                mma_bf16(acc[0][ib*2+1], aL[0], bh1);
                mma_bf16(acc[1][ib*2],   aL[1], bh0);
                mma_bf16(acc[1][ib*2+1], aL[1], bh1);
                mma_bf16(acc[0][ib*2],   aH[0], bl0);
                mma_bf16(acc[0][ib*2+1], aH[0], bl1);
                mma_bf16(acc[1][ib*2],   aH[1], bl0);
                mma_bf16(acc[1][ib*2+1], aH[1], bl1);
            }
        }
    }

    const int er = lane >> 2, ec = (lane & 3) * 2;
    if (mode == 0) {
        #pragma unroll
        for (int im = 0; im < 2; im++)
            #pragma unroll
            for (int in = 0; in < 8; in++) {
                const int n = n0 + wn + in * 8 + ec;
                const float bx = bias[n], by = bias[n + 1];
                const int mA = m0 + wm + im * 16 + er;
                float2 v0 = {acc[im][in][0] + bx, acc[im][in][1] + by};
                *reinterpret_cast<float2*>(Cf + (size_t)mA * HIDD + n) = v0;
                float2 v1 = {acc[im][in][2] + bx, acc[im][in][3] + by};
                *reinterpret_cast<float2*>(Cf + (size_t)(mA + 8) * HIDD + n) = v1;
            }
    } else {
        uint32_t* chiu = reinterpret_cast<uint32_t*>(ChiB + (size_t)z * MH);
        uint32_t* clou = reinterpret_cast<uint32_t*>(CloB + (size_t)z * MH);
        #pragma unroll
        for (int im = 0; im < 2; im++)
            #pragma unroll
            for (int in = 0; in < 8; in++) {
                const int n = n0 + wn + in * 8 + ec;
                const float bx = bias[n], by = bias[n + 1];
                const int mA = m0 + wm + im * 16 + er;
                float f0 = (acc[im][in][0] + bx) * scale;
                float f1 = (acc[im][in][1] + by) * scale;
                float f2 = (acc[im][in][2] + bx) * scale;
                float f3 = (acc[im][in][3] + by) * scale;
                size_t i0 = ((size_t)mA * HIDD + n) >> 1;
                size_t i1 = ((size_t)(mA + 8) * HIDD + n) >> 1;
                uint32_t h01 = cvt2bf(f0, f1), h23 = cvt2bf(f2, f3);
                chiu[i0] = h01;
                chiu[i1] = h23;
                clou[i0] = cvt2bf(f0 - bflo_f(h01), f1 - bfhi_f(h01));
                clou[i1] = cvt2bf(f2 - bflo_f(h23), f3 - bfhi_f(h23));
            }
    }
}

// ---------------------------------------------------------------------------
// HMMA flash attention: 128 threads / 4 warps, warp tile 32 q-rows x 64 kv.
// K/V fragment loads amortize over 2x MMAs (ldm/MMA 0.75 -> 0.42).
// 2-stage KV ring, 2 CTAs/SM, ex2-MUFU softmax, interleaved MMA.
// ---------------------------------------------------------------------------
#define APAD 72
#define SQ_H 0
#define SQ_L (128 * APAD)
#define SKV  (2 * 128 * APAD)
#define KVS_K_L (64 * APAD)
#define KVS_V_H (2 * 64 * APAD)
#define KVS_V_L (3 * 64 * APAD)
#define KV_STG (4 * 64 * APAD)
#define ASMEM_E (SKV + 2 * KV_STG)
#define ASMEM_B (ASMEM_E * 2)              // 110592 bytes
#define TKV (SS / 64)                      // 32

__global__ __launch_bounds__(128, 2) void attn_mma_kernel(
    const __nv_bfloat16* __restrict__ phi, const __nv_bfloat16* __restrict__ plo,
    __nv_bfloat16* __restrict__ chi, __nv_bfloat16* __restrict__ clo)
{
    extern __shared__ __nv_bfloat16 sm[];
    const uint32_t smb = smem_u32(sm);

    const int tid  = threadIdx.x;
    const int wid  = tid >> 5, lane = tid & 31;
    const int b    = blockIdx.y >> 4;
    const int h    = blockIdx.y & 15;
    const int q0   = blockIdx.x * 128;
    const int hoff = h * HDD;

    const __nv_bfloat16* qhi = phi;
    const __nv_bfloat16* qlo = plo;
    const __nv_bfloat16* khi = phi + MH;
    const __nv_bfloat16* klo = plo + MH;
    const __nv_bfloat16* vhi = phi + 2 * MH;
    const __nv_bfloat16* vlo = plo + 2 * MH;

    // ---- Q tile (own commit group; first wait0 covers it)
    {
        const size_t qg = ((size_t)b * SS + q0) * HIDD + hoff;
        #pragma unroll
        for (int i = 0; i < 8; i++) {
            int idx = tid + i * 128;            // 1024: 128 rows x 8 chunks
            int r = idx >> 3, ch = idx & 7;
            cp16(smb + (uint32_t)(SQ_H + r * APAD + ch * 8) * 2,
                 qhi + qg + (size_t)r * HIDD + ch * 8);
            cp16(smb + (uint32_t)(SQ_L + r * APAD + ch * 8) * 2,
                 qlo + qg + (size_t)r * HIDD + ch * 8);
        }
        cp_commit();
    }

    auto issue_kv = [&](int kt) {
        const uint32_t sb = smb + (uint32_t)(SKV + (kt & 1) * KV_STG) * 2;
        #pragma unroll
        for (int i = 0; i < 4; i++) {
            int idx = tid + i * 128;            // 512: 64 rows x 8 chunks
            int r = idx >> 3, ch = idx & 7;
            size_t g = ((size_t)b * SS + kt * 64 + r) * HIDD + hoff + ch * 8;
            uint32_t so = sb + (uint32_t)(r * APAD + ch * 8) * 2;
            cp16(so,                           khi + g);
            cp16(so + (uint32_t)KVS_K_L * 2,   klo + g);
            cp16(so + (uint32_t)KVS_V_H * 2,   vhi + g);
            cp16(so + (uint32_t)KVS_V_L * 2,   vlo + g);
        }
        cp_commit();
    };
    issue_kv(0);

    // warp owns q rows [wid*32, wid*32+32); m-frag im covers +im*16
    const uint32_t aRowOff = (uint32_t)((wid * 32 + (lane & 15)) * APAD +
                                        ((lane >> 4) << 3)) * 2;
    const uint32_t bRowOff = (uint32_t)(((lane & 7) + ((lane & 16) ? 8 : 0)) * APAD +
                                        ((lane & 8) ? 8 : 0)) * 2;
    const uint32_t vRowOff = (uint32_t)((lane & 15) * APAD +
                                        ((lane >> 4) << 3)) * 2;

    float O[2][8][4];
    #pragma unroll
    for (int im = 0; im < 2; im++)
        #pragma unroll
        for (int j = 0; j < 8; j++)
            #pragma unroll
            for (int t = 0; t < 4; t++) O[im][j][t] = 0.f;
    float mrow[2][2] = {{-1e30f, -1e30f}, {-1e30f, -1e30f}};
    float lrow[2][2] = {{0.f, 0.f}, {0.f, 0.f}};

    for (int kt = 0; kt < TKV; kt++) {
        cp_wait0();
        __syncthreads();        // copies visible AND prev-tile readers done
        if (kt + 1 < TKV) issue_kv(kt + 1);

        const uint32_t kvb = smb + (uint32_t)(SKV + (kt & 1) * KV_STG) * 2;

        // ---- S = Q K^T (3-term; K frags shared across both m-frags)
        float sf[2][8][4];
        #pragma unroll
        for (int im = 0; im < 2; im++)
            #pragma unroll
            for (int j = 0; j < 8; j++)
                #pragma unroll
                for (int t = 0; t < 4; t++) sf[im][j][t] = 0.f;

        #pragma unroll
        for (int kk = 0; kk < 4; kk++) {
            uint32_t qh[2][4], ql[2][4];
            #pragma unroll
            for (int im = 0; im < 2; im++) {
                ldm4(qh[im], smb + (uint32_t)SQ_H * 2 + aRowOff +
                             (uint32_t)(im * 16 * APAD) * 2 + kk * 32);
                ldm4(ql[im], smb + (uint32_t)SQ_L * 2 + aRowOff +
                             (uint32_t)(im * 16 * APAD) * 2 + kk * 32);
            }
            #pragma unroll
            for (int nb = 0; nb < 4; nb++) {
                uint32_t rh[4], rl[4];
                ldm4(rh, kvb + bRowOff + (uint32_t)(nb * 16 * APAD) * 2 + kk * 32);
                ldm4(rl, kvb + (uint32_t)KVS_K_L * 2 + bRowOff +
                          (uint32_t)(nb * 16 * APAD) * 2 + kk * 32);
                uint32_t bh0[2] = {rh[0], rh[1]}, bh1[2] = {rh[2], rh[3]};
                uint32_t bl0[2] = {rl[0], rl[1]}, bl1[2] = {rl[2], rl[3]};
                mma_bf16(sf[0][nb*2],   qh[0], bh0);
                mma_bf16(sf[0][nb*2+1], qh[0], bh1);
                mma_bf16(sf[1][nb*2],   qh[1], bh0);
                mma_bf16(sf[1][nb*2+1], qh[1], bh1);
                mma_bf16(sf[0][nb*2],   ql[0], bh0);
                mma_bf16(sf[0][nb*2+1], ql[0], bh1);
                mma_bf16(sf[1][nb*2],   ql[1], bh0);
                mma_bf16(sf[1][nb*2+1], ql[1], bh1);
                mma_bf16(sf[0][nb*2],   qh[0], bl0);
                mma_bf16(sf[0][nb*2+1], qh[0], bl1);
                mma_bf16(sf[1][nb*2],   qh[1], bl0);
                mma_bf16(sf[1][nb*2+1], qh[1], bl1);
            }
        }

        // ---- online softmax (exp2 domain, MUFU ex2), 4 rows per thread
        float cc[2][2];
        #pragma unroll
        for (int im = 0; im < 2; im++) {
            float mx0 = -1e30f, mx1 = -1e30f;
            #pragma unroll
            for (int j = 0; j < 8; j++) {
                mx0 = fmaxf(mx0, fmaxf(sf[im][j][0], sf[im][j][1]));
                mx1 = fmaxf(mx1, fmaxf(sf[im][j][2], sf[im][j][3]));
            }
            mx0 = fmaxf(mx0, __shfl_xor_sync(0xffffffffu, mx0, 1));
            mx0 = fmaxf(mx0, __shfl_xor_sync(0xffffffffu, mx0, 2));
            mx1 = fmaxf(mx1, __shfl_xor_sync(0xffffffffu, mx1, 1));
            mx1 = fmaxf(mx1, __shfl_xor_sync(0xffffffffu, mx1, 2));
            float mn0 = fmaxf(mrow[im][0], mx0);
            float mn1 = fmaxf(mrow[im][1], mx1);
            cc[im][0] = ex2(mrow[im][0] - mn0);
            cc[im][1] = ex2(mrow[im][1] - mn1);
            mrow[im][0] = mn0; mrow[im][1] = mn1;

            float rs0 = 0.f, rs1 = 0.f;
            #pragma unroll
            for (int j = 0; j < 8; j++) {
                sf[im][j][0] = ex2(sf[im][j][0] - mn0);
                sf[im][j][1] = ex2(sf[im][j][1] - mn0);
                sf[im][j][2] = ex2(sf[im][j][2] - mn1);
                sf[im][j][3] = ex2(sf[im][j][3] - mn1);
                rs0 += sf[im][j][0] + sf[im][j][1];
                rs1 += sf[im][j][2] + sf[im][j][3];
            }
            rs0 += __shfl_xor_sync(0xffffffffu, rs0, 1);
            rs0 += __shfl_xor_sync(0xffffffffu, rs0, 2);
            rs1 += __shfl_xor_sync(0xffffffffu, rs1, 1);
            rs1 += __shfl_xor_sync(0xffffffffu, rs1, 2);
            lrow[im][0] = lrow[im][0] * cc[im][0] + rs0;
            lrow[im][1] = lrow[im][1] * cc[im][1] + rs1;
        }

        if (__any_sync(0xffffffffu,
                       (cc[0][0] < 1.f) || (cc[0][1] < 1.f) ||
                       (cc[1][0] < 1.f) || (cc[1][1] < 1.f))) {
            #pragma unroll
            for (int im = 0; im < 2; im++)
                #pragma unroll
                for (int j = 0; j < 8; j++) {
                    O[im][j][0] *= cc[im][0]; O[im][j][1] *= cc[im][0];
                    O[im][j][2] *= cc[im][1]; O[im][j][3] *= cc[im][1];
                }
        }

        // ---- pack P hi/lo into A fragments (cvt.bf16x2-based)
        uint32_t ph01[2][8], ph23[2][8], pl01[2][8], pl23[2][8];
        #pragma unroll
        for (int im = 0; im < 2; im++)
            #pragma unroll
            for (int j = 0; j < 8; j++) {
                uint32_t h01 = cvt2bf(sf[im][j][0], sf[im][j][1]);
                uint32_t h23 = cvt2bf(sf[im][j][2], sf[im][j][3]);
                ph01[im][j] = h01;
                ph23[im][j] = h23;
                pl01[im][j] = cvt2bf(sf[im][j][0] - bflo_f(h01),
                                     sf[im][j][1] - bfhi_f(h01));
                pl23[im][j] = cvt2bf(sf[im][j][2] - bflo_f(h23),
                                     sf[im][j][3] - bfhi_f(h23));
            }

        // ---- O += P V (3-term; V frags shared across both m-frags)
        #pragma unroll
        for (int kk = 0; kk < 4; kk++) {
            uint32_t ah[2][4], al[2][4];
            #pragma unroll
            for (int im = 0; im < 2; im++) {
                ah[im][0] = ph01[im][2*kk];   ah[im][1] = ph23[im][2*kk];
                ah[im][2] = ph01[im][2*kk+1]; ah[im][3] = ph23[im][2*kk+1];
                al[im][0] = pl01[im][2*kk];   al[im][1] = pl23[im][2*kk];
                al[im][2] = pl01[im][2*kk+1]; al[im][3] = pl23[im][2*kk+1];
            }
            #pragma unroll
            for (int nb = 0; nb < 4; nb++) {
                uint32_t rh[4], rl[4];
                uint32_t voff = vRowOff + (uint32_t)(kk * 16 * APAD + nb * 16) * 2;
                ldm4t(rh, kvb + (uint32_t)KVS_V_H * 2 + voff);
                ldm4t(rl, kvb + (uint32_t)KVS_V_L * 2 + voff);
                uint32_t bh0[2] = {rh[0], rh[1]}, bh1[2] = {rh[2], rh[3]};
                uint32_t bl0[2] = {rl[0], rl[1]}, bl1[2] = {rl[2], rl[3]};
                mma_bf16(O[0][nb*2],   ah[0], bh0);
                mma_bf16(O[0][nb*2+1], ah[0], bh1);
                mma_bf16(O[1][nb*2],   ah[1], bh0);
                mma_bf16(O[1][nb*2+1], ah[1], bh1);
                mma_bf16(O[0][nb*2],   al[0], bh0);
                mma_bf16(O[0][nb*2+1], al[0], bh1);
                mma_bf16(O[1][nb*2],   al[1], bh0);
                mma_bf16(O[1][nb*2+1], al[1], bh1);
                mma_bf16(O[0][nb*2],   ah[0], bl0);
                mma_bf16(O[0][nb*2+1], ah[0], bl1);
                mma_bf16(O[1][nb*2],   ah[1], bl0);
                mma_bf16(O[1][nb*2+1], ah[1], bl1);
            }
        }
        // no end-of-loop barrier: next iteration's top barrier orders
        // stage overwrite (distance-1 issue) against this tile's readers
    }

    // ---- epilogue: ctx hi/lo (cvt-based)
    const int er = lane >> 2, ec = (lane & 3) * 2;
    uint32_t* chiu = reinterpret_cast<uint32_t*>(chi);
    uint32_t* clou = reinterpret_cast<uint32_t*>(clo);
    #pragma unroll
    for (int im = 0; im < 2; im++) {
        const float inv0 = 1.f / lrow[im][0], inv1 = 1.f / lrow[im][1];
        const int row0 = q0 + wid * 32 + im * 16 + er;
        #pragma unroll
        for (int j = 0; j < 8; j++) {
            const int col = hoff + j * 8 + ec;
            float f0 = O[im][j][0] * inv0, f1 = O[im][j][1] * inv0;
            float f2 = O[im][j][2] * inv1, f3 = O[im][j][3] * inv1;
            size_t i0 = (((size_t)b * SS + row0) * HIDD + col) >> 1;
            size_t i1 = (((size_t)b * SS + row0 + 8) * HIDD + col) >> 1;
            uint32_t h01 = cvt2bf(f0, f1), h23 = cvt2bf(f2, f3);
            chiu[i0] = h01;
            chiu[i1] = h23;
            clou[i0] = cvt2bf(f0 - bflo_f(h01), f1 - bfhi_f(h01));
            clou[i1] = cvt2bf(f2 - bflo_f(h23), f3 - bfhi_f(h23));
        }
    }
}

// ---------------------------------------------------------------------------

extern "C" void kernel_launch(void* const* d_in, const int* in_sizes, int n_in,
                              void* d_out, int out_size)
{
    const float* query = (const float*)d_in[0];
    const float* key_  = (const float*)d_in[1];
    const float* value = (const float*)d_in[2];
    const float* Wq    = (const float*)d_in[3];
    const float* bq    = (const float*)d_in[4];
    const float* Wk    = (const float*)d_in[5];
    const float* bk    = (const float*)d_in[6];
    const float* Wv    = (const float*)d_in[7];
    const float* bv    = (const float*)d_in[8];
    const float* Wo    = (const float*)d_in[9];
    const float* bo    = (const float*)d_in[10];
    float* out = (float*)d_out;

    __nv_bfloat16 *inhi, *inlo, *wthi, *wtlo, *phi, *plo, *chi, *clo;
    cudaGetSymbolAddress((void**)&inhi, g_inhi);
    cudaGetSymbolAddress((void**)&inlo, g_inlo);
    cudaGetSymbolAddress((void**)&wthi, g_wthi);
    cudaGetSymbolAddress((void**)&wtlo, g_wtlo);
    cudaGetSymbolAddress((void**)&phi, g_phi);
    cudaGetSymbolAddress((void**)&plo, g_plo);
    cudaGetSymbolAddress((void**)&chi, g_chi);
    cudaGetSymbolAddress((void**)&clo, g_clo);

    cudaFuncSetAttribute(mma_gemm_kernel,
                         cudaFuncAttributeMaxDynamicSharedMemorySize, GSMEM);
    cudaFuncSetAttribute(attn_mma_kernel,
                         cudaFuncAttributeMaxDynamicSharedMemorySize, ASMEM_B);

    const int n4 = (int)(MH / 4);
    const float qscale = 0.125f * 1.44269504088896f;  // 1/sqrt(HD) * log2(e)

    split3_kernel<<<dim3(n4 / 256, 3), 256>>>(query, key_, value, inhi, inlo, n4);
    splitT4_kernel<<<dim3(32, 32, 4), 256>>>(Wq, Wk, Wv, Wo, wthi, wtlo);

    // Q,K,V projections (grid.z = 3), 128x128 tiles
    mma_gemm_kernel<<<dim3(HIDD / 128, MM / 128, 3), 256, GSMEM>>>(
        inhi, inlo, wthi, wtlo, bq, bk, bv,
        nullptr, phi, plo, 1, qscale);

    attn_mma_kernel<<<dim3(SS / 128, BB * NHH), 128, ASMEM_B>>>(phi, plo, chi, clo);

    // output projection (weight slot 3, fp32 out)
    mma_gemm_kernel<<<dim3(HIDD / 128, MM / 128, 1), 256, GSMEM>>>(
        chi, clo, wthi + 3 * HH, wtlo + 3 * HH, bo, bo, bo,
        out, nullptr, nullptr, 0, 1.0f);
}

// round 14
// speedup vs baseline: 1.0438x; 1.0141x over previous
#include <cuda_runtime.h>
#include <cuda_bf16.h>
#include <stdint.h>
#include <math.h>

#define BB   2
#define SS   2048
#define HIDD 1024
#define NHH  16
#define HDD  64
#define MM   (BB * SS)   // 4096 rows

static constexpr size_t MH = (size_t)MM * HIDD;
static constexpr size_t HH = (size_t)HIDD * HIDD;

// ---------------------------------------------------------------------------
// Scratch (bf16 hi/lo everywhere)
// ---------------------------------------------------------------------------
__device__ __nv_bfloat16 g_inhi[3 * MH];
__device__ __nv_bfloat16 g_inlo[3 * MH];
__device__ __nv_bfloat16 g_wthi[4 * HH];
__device__ __nv_bfloat16 g_wtlo[4 * HH];
__device__ __nv_bfloat16 g_phi[3 * MH];
__device__ __nv_bfloat16 g_plo[3 * MH];
__device__ __nv_bfloat16 g_chi[MH];
__device__ __nv_bfloat16 g_clo[MH];

// ---------------------------------------------------------------------------
// PTX helpers
// ---------------------------------------------------------------------------
__device__ __forceinline__ uint32_t smem_u32(const void* p) {
    uint32_t a;
    asm("{ .reg .u64 t; cvta.to.shared.u64 t, %1; cvt.u32.u64 %0, t; }"
        : "=r"(a) : "l"(p));
    return a;
}
__device__ __forceinline__ void cp16(uint32_t saddr, const void* g) {
    asm volatile("cp.async.cg.shared.global [%0], [%1], 16;"
                 :: "r"(saddr), "l"(g) : "memory");
}
__device__ __forceinline__ void cp_commit() {
    asm volatile("cp.async.commit_group;" ::: "memory");
}
__device__ __forceinline__ void cp_wait0() {
    asm volatile("cp.async.wait_group 0;" ::: "memory");
}
__device__ __forceinline__ void ldm4(uint32_t* r, uint32_t addr) {
    asm volatile("ldmatrix.sync.aligned.m8n8.x4.shared.b16 {%0,%1,%2,%3}, [%4];"
                 : "=r"(r[0]), "=r"(r[1]), "=r"(r[2]), "=r"(r[3]) : "r"(addr));
}
__device__ __forceinline__ void ldm4t(uint32_t* r, uint32_t addr) {
    asm volatile("ldmatrix.sync.aligned.m8n8.x4.trans.shared.b16 {%0,%1,%2,%3}, [%4];"
                 : "=r"(r[0]), "=r"(r[1]), "=r"(r[2]), "=r"(r[3]) : "r"(addr));
}
__device__ __forceinline__ void mma_bf16(float* c, const uint32_t* a,
                                         const uint32_t* b) {
    asm volatile(
        "mma.sync.aligned.m16n8k16.row.col.f32.bf16.bf16.f32 "
        "{%0,%1,%2,%3}, {%4,%5,%6,%7}, {%8,%9}, {%0,%1,%2,%3};"
        : "+f"(c[0]), "+f"(c[1]), "+f"(c[2]), "+f"(c[3])
        : "r"(a[0]), "r"(a[1]), "r"(a[2]), "r"(a[3]), "r"(b[0]), "r"(b[1]));
}
// pack two floats -> bf16x2 {lo=a, hi=b} in ONE cvt
__device__ __forceinline__ uint32_t cvt2bf(float a, float b) {
    uint32_t r;
    asm("cvt.rn.bf16x2.f32 %0, %1, %2;" : "=r"(r) : "f"(b), "f"(a));
    return r;
}
__device__ __forceinline__ float bflo_f(uint32_t p) {
    return __uint_as_float(p << 16);
}
__device__ __forceinline__ float bfhi_f(uint32_t p) {
    return __uint_as_float(p & 0xffff0000u);
}
// guaranteed-MUFU exp2
__device__ __forceinline__ float ex2(float x) {
    float r;
    asm("ex2.approx.ftz.f32 %0, %1;" : "=f"(r) : "f"(x));
    return r;
}

// ---------------------------------------------------------------------------
// Batched fp32 -> bf16 hi/lo split (3 inputs via grid.y)
// ---------------------------------------------------------------------------
__global__ __launch_bounds__(256) void split3_kernel(
    const float* __restrict__ x0, const float* __restrict__ x1,
    const float* __restrict__ x2, __nv_bfloat16* __restrict__ hiB,
    __nv_bfloat16* __restrict__ loB, int n4)
{
    int i = blockIdx.x * 256 + threadIdx.x;
    if (i >= n4) return;
    const int z = blockIdx.y;
    const float* x = (z == 0) ? x0 : (z == 1) ? x1 : x2;
    float4 v = reinterpret_cast<const float4*>(x)[i];
    uint2 ho, llo;
    ho.x  = cvt2bf(v.x, v.y);
    ho.y  = cvt2bf(v.z, v.w);
    llo.x = cvt2bf(v.x - bflo_f(ho.x), v.y - bfhi_f(ho.x));
    llo.y = cvt2bf(v.z - bflo_f(ho.y), v.w - bfhi_f(ho.y));
    size_t base = (size_t)z * (MH / 4);
    reinterpret_cast<uint2*>(hiB)[base + i] = ho;
    reinterpret_cast<uint2*>(loB)[base + i] = llo;
}

// ---------------------------------------------------------------------------
// Batched W [K][N] fp32 -> W^T [N][K] bf16 hi/lo (4 weights via grid.z)
// ---------------------------------------------------------------------------
__global__ __launch_bounds__(256) void splitT4_kernel(
    const float* __restrict__ W0, const float* __restrict__ W1,
    const float* __restrict__ W2, const float* __restrict__ W3,
    __nv_bfloat16* __restrict__ ThB, __nv_bfloat16* __restrict__ TlB)
{
    __shared__ float t[32][33];
    const int z = blockIdx.z;
    const float* W = (z == 0) ? W0 : (z == 1) ? W1 : (z == 2) ? W2 : W3;
    __nv_bfloat16* Th = ThB + (size_t)z * HH;
    __nv_bfloat16* Tl = TlB + (size_t)z * HH;
    int n0 = blockIdx.x * 32, k0 = blockIdx.y * 32;
    int tx = threadIdx.x & 31, ty = threadIdx.x >> 5;
    #pragma unroll
    for (int i = 0; i < 4; i++)
        t[ty + i * 8][tx] = W[(size_t)(k0 + ty + i * 8) * HIDD + n0 + tx];
    __syncthreads();
    #pragma unroll
    for (int i = 0; i < 4; i++) {
        float x = t[tx][ty + i * 8];
        __nv_bfloat16 h = __float2bfloat16(x);
        __nv_bfloat16 l = __float2bfloat16(x - __bfloat162float(h));
        size_t o = (size_t)(n0 + ty + i * 8) * HIDD + k0 + tx;
        Th[o] = h;
        Tl[o] = l;
    }
}

// ---------------------------------------------------------------------------
// HMMA 3x-emulated GEMM: CTA tile 128x128, K-chunk 32, 2-stage ring,
// 2 CTAs/SM, B-fragment register double-buffer (LDSM/MMA overlap).
// ---------------------------------------------------------------------------
#define TPAD 40
#define TILE_E (128 * TPAD)
#define TILE_B (TILE_E * 2)        // 10240
#define STAGE_B (4 * TILE_B)       // 40960
#define GSMEM (2 * STAGE_B)        // 81920
#define NCHUNK (HIDD / 32)         // 32

__global__ __launch_bounds__(256, 2) void mma_gemm_kernel(
    const __nv_bfloat16* __restrict__ AhiB, const __nv_bfloat16* __restrict__ AloB,
    const __nv_bfloat16* __restrict__ BthB, const __nv_bfloat16* __restrict__ BtlB,
    const float* __restrict__ b0, const float* __restrict__ b1,
    const float* __restrict__ b2,
    float* __restrict__ Cf, __nv_bfloat16* __restrict__ ChiB,
    __nv_bfloat16* __restrict__ CloB, int mode, float scaleQ)
{
    extern __shared__ __nv_bfloat16 sm[];
    const uint32_t smb = smem_u32(sm);

    const int tid  = threadIdx.x;
    const int wid  = tid >> 5, lane = tid & 31;
    const int z    = blockIdx.z;
    const int m0   = blockIdx.y * 128, n0 = blockIdx.x * 128;
    const int wm   = (wid >> 1) * 32;
    const int wn   = (wid & 1) * 64;

    const __nv_bfloat16* Ahi = AhiB + (size_t)z * MH;
    const __nv_bfloat16* Alo = AloB + (size_t)z * MH;
    const __nv_bfloat16* Bth = BthB + (size_t)z * HH;
    const __nv_bfloat16* Btl = BtlB + (size_t)z * HH;
    const float* bias = (z == 0) ? b0 : (z == 1) ? b1 : b2;
    const float scale = (z == 0) ? scaleQ : 1.0f;

    const int lrow = tid >> 1;
    const int lcol = (tid & 1) * 16;
    const size_t gA = (size_t)(m0 + lrow) * HIDD + lcol;
    const size_t gB = (size_t)(n0 + lrow) * HIDD + lcol;
    const uint32_t sO = smb + (uint32_t)(lrow * TPAD + lcol) * 2;

    float acc[2][8][4];
    #pragma unroll
    for (int im = 0; im < 2; im++)
        #pragma unroll
        for (int in = 0; in < 8; in++)
            #pragma unroll
            for (int j = 0; j < 4; j++) acc[im][in][j] = 0.f;

    const uint32_t aOff = (uint32_t)((wm + (lane & 15)) * TPAD +
                                     ((lane >> 4) << 3)) * 2;
    const uint32_t bOff = (uint32_t)((wn + (lane & 7) + ((lane & 16) ? 8 : 0)) * TPAD +
                                     ((lane & 8) ? 8 : 0)) * 2;

    auto issue = [&](int kc) {
        uint32_t so = sO + (uint32_t)(kc & 1) * STAGE_B;
        size_t ga = gA + (size_t)kc * 32, gb = gB + (size_t)kc * 32;
        cp16(so,              Ahi + ga); cp16(so + 16,              Ahi + ga + 8);
        cp16(so + TILE_B,     Alo + ga); cp16(so + TILE_B + 16,     Alo + ga + 8);
        cp16(so + 2*TILE_B,   Bth + gb); cp16(so + 2*TILE_B + 16,   Bth + gb + 8);
        cp16(so + 3*TILE_B,   Btl + gb); cp16(so + 3*TILE_B + 16,   Btl + gb + 8);
        cp_commit();
    };
    issue(0);

    for (int kc = 0; kc < NCHUNK; kc++) {
        cp_wait0();
        __syncthreads();
        if (kc + 1 < NCHUNK) issue(kc + 1);

        const uint32_t st = smb + (uint32_t)(kc & 1) * STAGE_B;
        #pragma unroll
        for (int ks = 0; ks < 32; ks += 16) {
            uint32_t aH[2][4], aL[2][4];
            #pragma unroll
            for (int im = 0; im < 2; im++) {
                ldm4(aH[im], st + aOff + (uint32_t)(im * 16 * TPAD + ks) * 2);
                ldm4(aL[im], st + TILE_B + aOff + (uint32_t)(im * 16 * TPAD + ks) * 2);
            }
            // B-fragment register double-buffer: load ib+1 before MMAs of ib
            uint32_t rh[2][4], rl[2][4];
            ldm4(rh[0], st + 2*TILE_B + bOff + (uint32_t)ks * 2);
            ldm4(rl[0], st + 3*TILE_B + bOff + (uint32_t)ks * 2);
            #pragma unroll
            for (int ib = 0; ib < 4; ib++) {
                const int cur = ib & 1, nxt = cur ^ 1;
                if (ib < 3) {
                    ldm4(rh[nxt], st + 2*TILE_B + bOff +
                         (uint32_t)((ib + 1) * 16 * TPAD + ks) * 2);
                    ldm4(rl[nxt], st + 3*TILE_B + bOff +
                         (uint32_t)((ib + 1) * 16 * TPAD + ks) * 2);
                }
                uint32_t bh0[2] = {rh[cur][0], rh[cur][1]};
                uint32_t bh1[2] = {rh[cur][2], rh[cur][3]};
                uint32_t bl0[2] = {rl[cur][0], rl[cur][1]};
                uint32_t bl1[2] = {rl[cur][2], rl[cur][3]};
                mma_bf16(acc[0][ib*2],   aH[0], bh0);
                mma_bf16(acc[0][ib*2+1], aH[0], bh1);
                mma_bf16(acc[1][ib*2],   aH[1], bh0);
                mma_bf16(acc[1][ib*2+1], aH[1], bh1);
                mma_bf16(acc[0][ib*2],   aL[0], bh0);
                mma_bf16(acc[0][ib*2+1], aL[0], bh1);
                mma_bf16(acc[1][ib*2],   aL[1], bh0);
                mma_bf16(acc[1][ib*2+1], aL[1], bh1);
                mma_bf16(acc[0][ib*2],   aH[0], bl0);
                mma_bf16(acc[0][ib*2+1], aH[0], bl1);
                mma_bf16(acc[1][ib*2],   aH[1], bl0);
                mma_bf16(acc[1][ib*2+1], aH[1], bl1);
            }
        }
    }

    const int er = lane >> 2, ec = (lane & 3) * 2;
    if (mode == 0) {
        #pragma unroll
        for (int im = 0; im < 2; im++)
            #pragma unroll
            for (int in = 0; in < 8; in++) {
                const int n = n0 + wn + in * 8 + ec;
                const float bx = bias[n], by = bias[n + 1];
                const int mA = m0 + wm + im * 16 + er;
                float2 v0 = {acc[im][in][0] + bx, acc[im][in][1] + by};
                *reinterpret_cast<float2*>(Cf + (size_t)mA * HIDD + n) = v0;
                float2 v1 = {acc[im][in][2] + bx, acc[im][in][3] + by};
                *reinterpret_cast<float2*>(Cf + (size_t)(mA + 8) * HIDD + n) = v1;
            }
    } else {
        uint32_t* chiu = reinterpret_cast<uint32_t*>(ChiB + (size_t)z * MH);
        uint32_t* clou = reinterpret_cast<uint32_t*>(CloB + (size_t)z * MH);
        #pragma unroll
        for (int im = 0; im < 2; im++)
            #pragma unroll
            for (int in = 0; in < 8; in++) {
                const int n = n0 + wn + in * 8 + ec;
                const float bx = bias[n], by = bias[n + 1];
                const int mA = m0 + wm + im * 16 + er;
                float f0 = (acc[im][in][0] + bx) * scale;
                float f1 = (acc[im][in][1] + by) * scale;
                float f2 = (acc[im][in][2] + bx) * scale;
                float f3 = (acc[im][in][3] + by) * scale;
                size_t i0 = ((size_t)mA * HIDD + n) >> 1;
                size_t i1 = ((size_t)(mA + 8) * HIDD + n) >> 1;
                uint32_t h01 = cvt2bf(f0, f1), h23 = cvt2bf(f2, f3);
                chiu[i0] = h01;
                chiu[i1] = h23;
                clou[i0] = cvt2bf(f0 - bflo_f(h01), f1 - bfhi_f(h01));
                clou[i1] = cvt2bf(f2 - bflo_f(h23), f3 - bfhi_f(h23));
            }
    }
}

// ---------------------------------------------------------------------------
// HMMA flash attention: 128 threads / 4 warps, warp tile 32 q-rows x 64 kv.
// 2-stage KV ring, 2 CTAs/SM, ex2-MUFU softmax, K/V fragment register
// double-buffer (LDSM/MMA overlap).
// ---------------------------------------------------------------------------
#define APAD 72
#define SQ_H 0
#define SQ_L (128 * APAD)
#define SKV  (2 * 128 * APAD)
#define KVS_K_L (64 * APAD)
#define KVS_V_H (2 * 64 * APAD)
#define KVS_V_L (3 * 64 * APAD)
#define KV_STG (4 * 64 * APAD)
#define ASMEM_E (SKV + 2 * KV_STG)
#define ASMEM_B (ASMEM_E * 2)              // 110592 bytes
#define TKV (SS / 64)                      // 32

__global__ __launch_bounds__(128, 2) void attn_mma_kernel(
    const __nv_bfloat16* __restrict__ phi, const __nv_bfloat16* __restrict__ plo,
    __nv_bfloat16* __restrict__ chi, __nv_bfloat16* __restrict__ clo)
{
    extern __shared__ __nv_bfloat16 sm[];
    const uint32_t smb = smem_u32(sm);

    const int tid  = threadIdx.x;
    const int wid  = tid >> 5, lane = tid & 31;
    const int b    = blockIdx.y >> 4;
    const int h    = blockIdx.y & 15;
    const int q0   = blockIdx.x * 128;
    const int hoff = h * HDD;

    const __nv_bfloat16* qhi = phi;
    const __nv_bfloat16* qlo = plo;
    const __nv_bfloat16* khi = phi + MH;
    const __nv_bfloat16* klo = plo + MH;
    const __nv_bfloat16* vhi = phi + 2 * MH;
    const __nv_bfloat16* vlo = plo + 2 * MH;

    // ---- Q tile (own commit group; first wait0 covers it)
    {
        const size_t qg = ((size_t)b * SS + q0) * HIDD + hoff;
        #pragma unroll
        for (int i = 0; i < 8; i++) {
            int idx = tid + i * 128;            // 1024: 128 rows x 8 chunks
            int r = idx >> 3, ch = idx & 7;
            cp16(smb + (uint32_t)(SQ_H + r * APAD + ch * 8) * 2,
                 qhi + qg + (size_t)r * HIDD + ch * 8);
            cp16(smb + (uint32_t)(SQ_L + r * APAD + ch * 8) * 2,
                 qlo + qg + (size_t)r * HIDD + ch * 8);
        }
        cp_commit();
    }

    auto issue_kv = [&](int kt) {
        const uint32_t sb = smb + (uint32_t)(SKV + (kt & 1) * KV_STG) * 2;
        #pragma unroll
        for (int i = 0; i < 4; i++) {
            int idx = tid + i * 128;            // 512: 64 rows x 8 chunks
            int r = idx >> 3, ch = idx & 7;
            size_t g = ((size_t)b * SS + kt * 64 + r) * HIDD + hoff + ch * 8;
            uint32_t so = sb + (uint32_t)(r * APAD + ch * 8) * 2;
            cp16(so,                           khi + g);
            cp16(so + (uint32_t)KVS_K_L * 2,   klo + g);
            cp16(so + (uint32_t)KVS_V_H * 2,   vhi + g);
            cp16(so + (uint32_t)KVS_V_L * 2,   vlo + g);
        }
        cp_commit();
    };
    issue_kv(0);

    // warp owns q rows [wid*32, wid*32+32); m-frag im covers +im*16
    const uint32_t aRowOff = (uint32_t)((wid * 32 + (lane & 15)) * APAD +
                                        ((lane >> 4) << 3)) * 2;
    const uint32_t bRowOff = (uint32_t)(((lane & 7) + ((lane & 16) ? 8 : 0)) * APAD +
                                        ((lane & 8) ? 8 : 0)) * 2;
    const uint32_t vRowOff = (uint32_t)((lane & 15) * APAD +
                                        ((lane >> 4) << 3)) * 2;

    float O[2][8][4];
    #pragma unroll
    for (int im = 0; im < 2; im++)
        #pragma unroll
        for (int j = 0; j < 8; j++)
            #pragma unroll
            for (int t = 0; t < 4; t++) O[im][j][t] = 0.f;
    float mrow[2][2] = {{-1e30f, -1e30f}, {-1e30f, -1e30f}};
    float lrow[2][2] = {{0.f, 0.f}, {0.f, 0.f}};

    for (int kt = 0; kt < TKV; kt++) {
        cp_wait0();
        __syncthreads();        // copies visible AND prev-tile readers done
        if (kt + 1 < TKV) issue_kv(kt + 1);

        const uint32_t kvb = smb + (uint32_t)(SKV + (kt & 1) * KV_STG) * 2;

        // ---- S = Q K^T (3-term; K frags double-buffered in registers)
        float sf[2][8][4];
        #pragma unroll
        for (int im = 0; im < 2; im++)
            #pragma unroll
            for (int j = 0; j < 8; j++)
                #pragma unroll
                for (int t = 0; t < 4; t++) sf[im][j][t] = 0.f;

        #pragma unroll
        for (int kk = 0; kk < 4; kk++) {
            uint32_t qh[2][4], ql[2][4];
            #pragma unroll
            for (int im = 0; im < 2; im++) {
                ldm4(qh[im], smb + (uint32_t)SQ_H * 2 + aRowOff +
                             (uint32_t)(im * 16 * APAD) * 2 + kk * 32);
                ldm4(ql[im], smb + (uint32_t)SQ_L * 2 + aRowOff +
                             (uint32_t)(im * 16 * APAD) * 2 + kk * 32);
            }
            uint32_t rh[2][4], rl[2][4];
            ldm4(rh[0], kvb + bRowOff + kk * 32);
            ldm4(rl[0], kvb + (uint32_t)KVS_K_L * 2 + bRowOff + kk * 32);
            #pragma unroll
            for (int nb = 0; nb < 4; nb++) {
                const int cur = nb & 1, nxt = cur ^ 1;
                if (nb < 3) {
                    ldm4(rh[nxt], kvb + bRowOff +
                         (uint32_t)((nb + 1) * 16 * APAD) * 2 + kk * 32);
                    ldm4(rl[nxt], kvb + (uint32_t)KVS_K_L * 2 + bRowOff +
                         (uint32_t)((nb + 1) * 16 * APAD) * 2 + kk * 32);
                }
                uint32_t bh0[2] = {rh[cur][0], rh[cur][1]};
                uint32_t bh1[2] = {rh[cur][2], rh[cur][3]};
                uint32_t bl0[2] = {rl[cur][0], rl[cur][1]};
                uint32_t bl1[2] = {rl[cur][2], rl[cur][3]};
                mma_bf16(sf[0][nb*2],   qh[0], bh0);
                mma_bf16(sf[0][nb*2+1], qh[0], bh1);
                mma_bf16(sf[1][nb*2],   qh[1], bh0);
                mma_bf16(sf[1][nb*2+1], qh[1], bh1);
                mma_bf16(sf[0][nb*2],   ql[0], bh0);
                mma_bf16(sf[0][nb*2+1], ql[0], bh1);
                mma_bf16(sf[1][nb*2],   ql[1], bh0);
                mma_bf16(sf[1][nb*2+1], ql[1], bh1);
                mma_bf16(sf[0][nb*2],   qh[0], bl0);
                mma_bf16(sf[0][nb*2+1], qh[0], bl1);
                mma_bf16(sf[1][nb*2],   qh[1], bl0);
                mma_bf16(sf[1][nb*2+1], qh[1], bl1);
            }
        }

        // ---- online softmax (exp2 domain, MUFU ex2), 4 rows per thread
        float cc[2][2];
        #pragma unroll
        for (int im = 0; im < 2; im++) {
            float mx0 = -1e30f, mx1 = -1e30f;
            #pragma unroll
            for (int j = 0; j < 8; j++) {
                mx0 = fmaxf(mx0, fmaxf(sf[im][j][0], sf[im][j][1]));
                mx1 = fmaxf(mx1, fmaxf(sf[im][j][2], sf[im][j][3]));
            }
            mx0 = fmaxf(mx0, __shfl_xor_sync(0xffffffffu, mx0, 1));
            mx0 = fmaxf(mx0, __shfl_xor_sync(0xffffffffu, mx0, 2));
            mx1 = fmaxf(mx1, __shfl_xor_sync(0xffffffffu, mx1, 1));
            mx1 = fmaxf(mx1, __shfl_xor_sync(0xffffffffu, mx1, 2));
            float mn0 = fmaxf(mrow[im][0], mx0);
            float mn1 = fmaxf(mrow[im][1], mx1);
            cc[im][0] = ex2(mrow[im][0] - mn0);
            cc[im][1] = ex2(mrow[im][1] - mn1);
            mrow[im][0] = mn0; mrow[im][1] = mn1;

            float rs0 = 0.f, rs1 = 0.f;
            #pragma unroll
            for (int j = 0; j < 8; j++) {
                sf[im][j][0] = ex2(sf[im][j][0] - mn0);
                sf[im][j][1] = ex2(sf[im][j][1] - mn0);
                sf[im][j][2] = ex2(sf[im][j][2] - mn1);
                sf[im][j][3] = ex2(sf[im][j][3] - mn1);
                rs0 += sf[im][j][0] + sf[im][j][1];
                rs1 += sf[im][j][2] + sf[im][j][3];
            }
            rs0 += __shfl_xor_sync(0xffffffffu, rs0, 1);
            rs0 += __shfl_xor_sync(0xffffffffu, rs0, 2);
            rs1 += __shfl_xor_sync(0xffffffffu, rs1, 1);
            rs1 += __shfl_xor_sync(0xffffffffu, rs1, 2);
            lrow[im][0] = lrow[im][0] * cc[im][0] + rs0;
            lrow[im][1] = lrow[im][1] * cc[im][1] + rs1;
        }

        if (__any_sync(0xffffffffu,
                       (cc[0][0] < 1.f) || (cc[0][1] < 1.f) ||
                       (cc[1][0] < 1.f) || (cc[1][1] < 1.f))) {
            #pragma unroll
            for (int im = 0; im < 2; im++)
                #pragma unroll
                for (int j = 0; j < 8; j++) {
                    O[im][j][0] *= cc[im][0]; O[im][j][1] *= cc[im][0];
                    O[im][j][2] *= cc[im][1]; O[im][j][3] *= cc[im][1];
                }
        }

        // ---- pack P hi/lo into A fragments (cvt.bf16x2-based)
        uint32_t ph01[2][8], ph23[2][8], pl01[2][8], pl23[2][8];
        #pragma unroll
        for (int im = 0; im < 2; im++)
            #pragma unroll
            for (int j = 0; j < 8; j++) {
                uint32_t h01 = cvt2bf(sf[im][j][0], sf[im][j][1]);
                uint32_t h23 = cvt2bf(sf[im][j][2], sf[im][j][3]);
                ph01[im][j] = h01;
                ph23[im][j] = h23;
                pl01[im][j] = cvt2bf(sf[im][j][0] - bflo_f(h01),
                                     sf[im][j][1] - bfhi_f(h01));
                pl23[im][j] = cvt2bf(sf[im][j][2] - bflo_f(h23),
                                     sf[im][j][3] - bfhi_f(h23));
            }

        // ---- O += P V (3-term; V frags double-buffered in registers)
        #pragma unroll
        for (int kk = 0; kk < 4; kk++) {
            uint32_t ah[2][4], al[2][4];
            #pragma unroll
            for (int im = 0; im < 2; im++) {
                ah[im][0] = ph01[im][2*kk];   ah[im][1] = ph23[im][2*kk];
                ah[im][2] = ph01[im][2*kk+1]; ah[im][3] = ph23[im][2*kk+1];
                al[im][0] = pl01[im][2*kk];   al[im][1] = pl23[im][2*kk];
                al[im][2] = pl01[im][2*kk+1]; al[im][3] = pl23[im][2*kk+1];
            }
            uint32_t rh[2][4], rl[2][4];
            ldm4t(rh[0], kvb + (uint32_t)KVS_V_H * 2 + vRowOff +
                          (uint32_t)(kk * 16 * APAD) * 2);
            ldm4t(rl[0], kvb + (uint32_t)KVS_V_L * 2 + vRowOff +
                          (uint32_t)(kk * 16 * APAD) * 2);
            #pragma unroll
            for (int nb = 0; nb < 4; nb++) {
                const int cur = nb & 1, nxt = cur ^ 1;
                if (nb < 3) {
                    uint32_t voffn = vRowOff +
                        (uint32_t)(kk * 16 * APAD + (nb + 1) * 16) * 2;
                    ldm4t(rh[nxt], kvb + (uint32_t)KVS_V_H * 2 + voffn);
                    ldm4t(rl[nxt], kvb + (uint32_t)KVS_V_L * 2 + voffn);
                }
                uint32_t bh0[2] = {rh[cur][0], rh[cur][1]};
                uint32_t bh1[2] = {rh[cur][2], rh[cur][3]};
                uint32_t bl0[2] = {rl[cur][0], rl[cur][1]};
                uint32_t bl1[2] = {rl[cur][2], rl[cur][3]};
                mma_bf16(O[0][nb*2],   ah[0], bh0);
                mma_bf16(O[0][nb*2+1], ah[0], bh1);
                mma_bf16(O[1][nb*2],   ah[1], bh0);
                mma_bf16(O[1][nb*2+1], ah[1], bh1);
                mma_bf16(O[0][nb*2],   al[0], bh0);
                mma_bf16(O[0][nb*2+1], al[0], bh1);
                mma_bf16(O[1][nb*2],   al[1], bh0);
                mma_bf16(O[1][nb*2+1], al[1], bh1);
                mma_bf16(O[0][nb*2],   ah[0], bl0);
                mma_bf16(O[0][nb*2+1], ah[0], bl1);
                mma_bf16(O[1][nb*2],   ah[1], bl0);
                mma_bf16(O[1][nb*2+1], ah[1], bl1);
            }
        }
        // no end-of-loop barrier: next iteration's top barrier orders
        // stage overwrite (distance-1 issue) against this tile's readers
    }

    // ---- epilogue: ctx hi/lo (cvt-based)
    const int er = lane >> 2, ec = (lane & 3) * 2;
    uint32_t* chiu = reinterpret_cast<uint32_t*>(chi);
    uint32_t* clou = reinterpret_cast<uint32_t*>(clo);
    #pragma unroll
    for (int im = 0; im < 2; im++) {
        const float inv0 = 1.f / lrow[im][0], inv1 = 1.f / lrow[im][1];
        const int row0 = q0 + wid * 32 + im * 16 + er;
        #pragma unroll
        for (int j = 0; j < 8; j++) {
            const int col = hoff + j * 8 + ec;
            float f0 = O[im][j][0] * inv0, f1 = O[im][j][1] * inv0;
            float f2 = O[im][j][2] * inv1, f3 = O[im][j][3] * inv1;
            size_t i0 = (((size_t)b * SS + row0) * HIDD + col) >> 1;
            size_t i1 = (((size_t)b * SS + row0 + 8) * HIDD + col) >> 1;
            uint32_t h01 = cvt2bf(f0, f1), h23 = cvt2bf(f2, f3);
            chiu[i0] = h01;
            chiu[i1] = h23;
            clou[i0] = cvt2bf(f0 - bflo_f(h01), f1 - bfhi_f(h01));
            clou[i1] = cvt2bf(f2 - bflo_f(h23), f3 - bfhi_f(h23));
        }
    }
}

// ---------------------------------------------------------------------------

extern "C" void kernel_launch(void* const* d_in, const int* in_sizes, int n_in,
                              void* d_out, int out_size)
{
    const float* query = (const float*)d_in[0];
    const float* key_  = (const float*)d_in[1];
    const float* value = (const float*)d_in[2];
    const float* Wq    = (const float*)d_in[3];
    const float* bq    = (const float*)d_in[4];
    const float* Wk    = (const float*)d_in[5];
    const float* bk    = (const float*)d_in[6];
    const float* Wv    = (const float*)d_in[7];
    const float* bv    = (const float*)d_in[8];
    const float* Wo    = (const float*)d_in[9];
    const float* bo    = (const float*)d_in[10];
    float* out = (float*)d_out;

    __nv_bfloat16 *inhi, *inlo, *wthi, *wtlo, *phi, *plo, *chi, *clo;
    cudaGetSymbolAddress((void**)&inhi, g_inhi);
    cudaGetSymbolAddress((void**)&inlo, g_inlo);
    cudaGetSymbolAddress((void**)&wthi, g_wthi);
    cudaGetSymbolAddress((void**)&wtlo, g_wtlo);
    cudaGetSymbolAddress((void**)&phi, g_phi);
    cudaGetSymbolAddress((void**)&plo, g_plo);
    cudaGetSymbolAddress((void**)&chi, g_chi);
    cudaGetSymbolAddress((void**)&clo, g_clo);

    cudaFuncSetAttribute(mma_gemm_kernel,
                         cudaFuncAttributeMaxDynamicSharedMemorySize, GSMEM);
    cudaFuncSetAttribute(attn_mma_kernel,
                         cudaFuncAttributeMaxDynamicSharedMemorySize, ASMEM_B);

    const int n4 = (int)(MH / 4);
    const float qscale = 0.125f * 1.44269504088896f;  // 1/sqrt(HD) * log2(e)

    split3_kernel<<<dim3(n4 / 256, 3), 256>>>(query, key_, value, inhi, inlo, n4);
    splitT4_kernel<<<dim3(32, 32, 4), 256>>>(Wq, Wk, Wv, Wo, wthi, wtlo);

    // Q,K,V projections (grid.z = 3), 128x128 tiles
    mma_gemm_kernel<<<dim3(HIDD / 128, MM / 128, 3), 256, GSMEM>>>(
        inhi, inlo, wthi, wtlo, bq, bk, bv,
        nullptr, phi, plo, 1, qscale);

    attn_mma_kernel<<<dim3(SS / 128, BB * NHH), 128, ASMEM_B>>>(phi, plo, chi, clo);

    // output projection (weight slot 3, fp32 out)
    mma_gemm_kernel<<<dim3(HIDD / 128, MM / 128, 1), 256, GSMEM>>>(
        chi, clo, wthi + 3 * HH, wtlo + 3 * HH, bo, bo, bo,
        out, nullptr, nullptr, 0, 1.0f);
}

// round 17
// speedup vs baseline: 1.0444x; 1.0006x over previous
#include <cuda_runtime.h>
#include <cuda_bf16.h>
#include <stdint.h>
#include <math.h>

#define BB   2
#define SS   2048
#define HIDD 1024
#define NHH  16
#define HDD  64
#define MM   (BB * SS)   // 4096 rows

static constexpr size_t MH = (size_t)MM * HIDD;
static constexpr size_t HH = (size_t)HIDD * HIDD;

// ---------------------------------------------------------------------------
// Scratch (bf16 hi/lo everywhere)
// ---------------------------------------------------------------------------
__device__ __nv_bfloat16 g_inhi[3 * MH];
__device__ __nv_bfloat16 g_inlo[3 * MH];
__device__ __nv_bfloat16 g_wthi[4 * HH];
__device__ __nv_bfloat16 g_wtlo[4 * HH];
__device__ __nv_bfloat16 g_phi[3 * MH];
__device__ __nv_bfloat16 g_plo[3 * MH];
__device__ __nv_bfloat16 g_chi[MH];
__device__ __nv_bfloat16 g_clo[MH];

// ---------------------------------------------------------------------------
// PTX helpers
// ---------------------------------------------------------------------------
__device__ __forceinline__ uint32_t smem_u32(const void* p) {
    uint32_t a;
    asm("{ .reg .u64 t; cvta.to.shared.u64 t, %1; cvt.u32.u64 %0, t; }"
        : "=r"(a) : "l"(p));
    return a;
}
__device__ __forceinline__ void cp16(uint32_t saddr, const void* g) {
    asm volatile("cp.async.cg.shared.global [%0], [%1], 16;"
                 :: "r"(saddr), "l"(g) : "memory");
}
__device__ __forceinline__ void cp_commit() {
    asm volatile("cp.async.commit_group;" ::: "memory");
}
__device__ __forceinline__ void cp_wait0() {
    asm volatile("cp.async.wait_group 0;" ::: "memory");
}
__device__ __forceinline__ void ldm4(uint32_t* r, uint32_t addr) {
    asm volatile("ldmatrix.sync.aligned.m8n8.x4.shared.b16 {%0,%1,%2,%3}, [%4];"
                 : "=r"(r[0]), "=r"(r[1]), "=r"(r[2]), "=r"(r[3]) : "r"(addr));
}
__device__ __forceinline__ void ldm4t(uint32_t* r, uint32_t addr) {
    asm volatile("ldmatrix.sync.aligned.m8n8.x4.trans.shared.b16 {%0,%1,%2,%3}, [%4];"
                 : "=r"(r[0]), "=r"(r[1]), "=r"(r[2]), "=r"(r[3]) : "r"(addr));
}
__device__ __forceinline__ void mma_bf16(float* c, const uint32_t* a,
                                         const uint32_t* b) {
    asm volatile(
        "mma.sync.aligned.m16n8k16.row.col.f32.bf16.bf16.f32 "
        "{%0,%1,%2,%3}, {%4,%5,%6,%7}, {%8,%9}, {%0,%1,%2,%3};"
        : "+f"(c[0]), "+f"(c[1]), "+f"(c[2]), "+f"(c[3])
        : "r"(a[0]), "r"(a[1]), "r"(a[2]), "r"(a[3]), "r"(b[0]), "r"(b[1]));
}
// pack two floats -> bf16x2 {lo=a, hi=b} in ONE cvt
__device__ __forceinline__ uint32_t cvt2bf(float a, float b) {
    uint32_t r;
    asm("cvt.rn.bf16x2.f32 %0, %1, %2;" : "=r"(r) : "f"(b), "f"(a));
    return r;
}
__device__ __forceinline__ float bflo_f(uint32_t p) {
    return __uint_as_float(p << 16);
}
__device__ __forceinline__ float bfhi_f(uint32_t p) {
    return __uint_as_float(p & 0xffff0000u);
}
// guaranteed-MUFU exp2
__device__ __forceinline__ float ex2(float x) {
    float r;
    asm("ex2.approx.ftz.f32 %0, %1;" : "=f"(r) : "f"(x));
    return r;
}

// ---------------------------------------------------------------------------
// Batched fp32 -> bf16 hi/lo split (3 inputs via grid.y)
// ---------------------------------------------------------------------------
__global__ __launch_bounds__(256) void split3_kernel(
    const float* __restrict__ x0, const float* __restrict__ x1,
    const float* __restrict__ x2, __nv_bfloat16* __restrict__ hiB,
    __nv_bfloat16* __restrict__ loB, int n4)
{
    int i = blockIdx.x * 256 + threadIdx.x;
    if (i >= n4) return;
    const int z = blockIdx.y;
    const float* x = (z == 0) ? x0 : (z == 1) ? x1 : x2;
    float4 v = reinterpret_cast<const float4*>(x)[i];
    uint2 ho, llo;
    ho.x  = cvt2bf(v.x, v.y);
    ho.y  = cvt2bf(v.z, v.w);
    llo.x = cvt2bf(v.x - bflo_f(ho.x), v.y - bfhi_f(ho.x));
    llo.y = cvt2bf(v.z - bflo_f(ho.y), v.w - bfhi_f(ho.y));
    size_t base = (size_t)z * (MH / 4);
    reinterpret_cast<uint2*>(hiB)[base + i] = ho;
    reinterpret_cast<uint2*>(loB)[base + i] = llo;
}

// ---------------------------------------------------------------------------
// Batched W [K][N] fp32 -> W^T [N][K] bf16 hi/lo (4 weights via grid.z)
// ---------------------------------------------------------------------------
__global__ __launch_bounds__(256) void splitT4_kernel(
    const float* __restrict__ W0, const float* __restrict__ W1,
    const float* __restrict__ W2, const float* __restrict__ W3,
    __nv_bfloat16* __restrict__ ThB, __nv_bfloat16* __restrict__ TlB)
{
    __shared__ float t[32][33];
    const int z = blockIdx.z;
    const float* W = (z == 0) ? W0 : (z == 1) ? W1 : (z == 2) ? W2 : W3;
    __nv_bfloat16* Th = ThB + (size_t)z * HH;
    __nv_bfloat16* Tl = TlB + (size_t)z * HH;
    int n0 = blockIdx.x * 32, k0 = blockIdx.y * 32;
    int tx = threadIdx.x & 31, ty = threadIdx.x >> 5;
    #pragma unroll
    for (int i = 0; i < 4; i++)
        t[ty + i * 8][tx] = W[(size_t)(k0 + ty + i * 8) * HIDD + n0 + tx];
    __syncthreads();
    #pragma unroll
    for (int i = 0; i < 4; i++) {
        float x = t[tx][ty + i * 8];
        __nv_bfloat16 h = __float2bfloat16(x);
        __nv_bfloat16 l = __float2bfloat16(x - __bfloat162float(h));
        size_t o = (size_t)(n0 + ty + i * 8) * HIDD + k0 + tx;
        Th[o] = h;
        Tl[o] = l;
    }
}

// ---------------------------------------------------------------------------
// HMMA 3x-emulated GEMM: CTA tile 128x128, K-chunk 32, 2-stage ring,
// 2 CTAs/SM, B-fragment register double-buffer (round-14 proven version).
// ---------------------------------------------------------------------------
#define TPAD 40
#define TILE_E (128 * TPAD)
#define TILE_B (TILE_E * 2)        // 10240
#define STAGE_B (4 * TILE_B)       // 40960
#define GSMEM (2 * STAGE_B)        // 81920
#define NCHUNK (HIDD / 32)         // 32

__global__ __launch_bounds__(256, 2) void mma_gemm_kernel(
    const __nv_bfloat16* __restrict__ AhiB, const __nv_bfloat16* __restrict__ AloB,
    const __nv_bfloat16* __restrict__ BthB, const __nv_bfloat16* __restrict__ BtlB,
    const float* __restrict__ b0, const float* __restrict__ b1,
    const float* __restrict__ b2,
    float* __restrict__ Cf, __nv_bfloat16* __restrict__ ChiB,
    __nv_bfloat16* __restrict__ CloB, int mode, float scaleQ)
{
    extern __shared__ __nv_bfloat16 sm[];
    const uint32_t smb = smem_u32(sm);

    const int tid  = threadIdx.x;
    const int wid  = tid >> 5, lane = tid & 31;
    const int z    = blockIdx.z;
    const int m0   = blockIdx.y * 128, n0 = blockIdx.x * 128;
    const int wm   = (wid >> 1) * 32;
    const int wn   = (wid & 1) * 64;

    const __nv_bfloat16* Ahi = AhiB + (size_t)z * MH;
    const __nv_bfloat16* Alo = AloB + (size_t)z * MH;
    const __nv_bfloat16* Bth = BthB + (size_t)z * HH;
    const __nv_bfloat16* Btl = BtlB + (size_t)z * HH;
    const float* bias = (z == 0) ? b0 : (z == 1) ? b1 : b2;
    const float scale = (z == 0) ? scaleQ : 1.0f;

    const int lrow = tid >> 1;
    const int lcol = (tid & 1) * 16;
    const size_t gA = (size_t)(m0 + lrow) * HIDD + lcol;
    const size_t gB = (size_t)(n0 + lrow) * HIDD + lcol;
    const uint32_t sO = smb + (uint32_t)(lrow * TPAD + lcol) * 2;

    float acc[2][8][4];
    #pragma unroll
    for (int im = 0; im < 2; im++)
        #pragma unroll
        for (int in = 0; in < 8; in++)
            #pragma unroll
            for (int j = 0; j < 4; j++) acc[im][in][j] = 0.f;

    const uint32_t aOff = (uint32_t)((wm + (lane & 15)) * TPAD +
                                     ((lane >> 4) << 3)) * 2;
    const uint32_t bOff = (uint32_t)((wn + (lane & 7) + ((lane & 16) ? 8 : 0)) * TPAD +
                                     ((lane & 8) ? 8 : 0)) * 2;

    auto issue = [&](int kc) {
        uint32_t so = sO + (uint32_t)(kc & 1) * STAGE_B;
        size_t ga = gA + (size_t)kc * 32, gb = gB + (size_t)kc * 32;
        cp16(so,              Ahi + ga); cp16(so + 16,              Ahi + ga + 8);
        cp16(so + TILE_B,     Alo + ga); cp16(so + TILE_B + 16,     Alo + ga + 8);
        cp16(so + 2*TILE_B,   Bth + gb); cp16(so + 2*TILE_B + 16,   Bth + gb + 8);
        cp16(so + 3*TILE_B,   Btl + gb); cp16(so + 3*TILE_B + 16,   Btl + gb + 8);
        cp_commit();
    };
    issue(0);

    for (int kc = 0; kc < NCHUNK; kc++) {
        cp_wait0();
        __syncthreads();
        if (kc + 1 < NCHUNK) issue(kc + 1);

        const uint32_t st = smb + (uint32_t)(kc & 1) * STAGE_B;
        #pragma unroll
        for (int ks = 0; ks < 32; ks += 16) {
            uint32_t aH[2][4], aL[2][4];
            #pragma unroll
            for (int im = 0; im < 2; im++) {
                ldm4(aH[im], st + aOff + (uint32_t)(im * 16 * TPAD + ks) * 2);
                ldm4(aL[im], st + TILE_B + aOff + (uint32_t)(im * 16 * TPAD + ks) * 2);
            }
            uint32_t rh[2][4], rl[2][4];
            ldm4(rh[0], st + 2*TILE_B + bOff + (uint32_t)ks * 2);
            ldm4(rl[0], st + 3*TILE_B + bOff + (uint32_t)ks * 2);
            #pragma unroll
            for (int ib = 0; ib < 4; ib++) {
                const int cur = ib & 1, nxt = cur ^ 1;
                if (ib < 3) {
                    ldm4(rh[nxt], st + 2*TILE_B + bOff +
                         (uint32_t)((ib + 1) * 16 * TPAD + ks) * 2);
                    ldm4(rl[nxt], st + 3*TILE_B + bOff +
                         (uint32_t)((ib + 1) * 16 * TPAD + ks) * 2);
                }
                uint32_t bh0[2] = {rh[cur][0], rh[cur][1]};
                uint32_t bh1[2] = {rh[cur][2], rh[cur][3]};
                uint32_t bl0[2] = {rl[cur][0], rl[cur][1]};
                uint32_t bl1[2] = {rl[cur][2], rl[cur][3]};
                mma_bf16(acc[0][ib*2],   aH[0], bh0);
                mma_bf16(acc[0][ib*2+1], aH[0], bh1);
                mma_bf16(acc[1][ib*2],   aH[1], bh0);
                mma_bf16(acc[1][ib*2+1], aH[1], bh1);
                mma_bf16(acc[0][ib*2],   aL[0], bh0);
                mma_bf16(acc[0][ib*2+1], aL[0], bh1);
                mma_bf16(acc[1][ib*2],   aL[1], bh0);
                mma_bf16(acc[1][ib*2+1], aL[1], bh1);
                mma_bf16(acc[0][ib*2],   aH[0], bl0);
                mma_bf16(acc[0][ib*2+1], aH[0], bl1);
                mma_bf16(acc[1][ib*2],   aH[1], bl0);
                mma_bf16(acc[1][ib*2+1], aH[1], bl1);
            }
        }
    }

    const int er = lane >> 2, ec = (lane & 3) * 2;
    if (mode == 0) {
        #pragma unroll
        for (int im = 0; im < 2; im++)
            #pragma unroll
            for (int in = 0; in < 8; in++) {
                const int n = n0 + wn + in * 8 + ec;
                const float bx = bias[n], by = bias[n + 1];
                const int mA = m0 + wm + im * 16 + er;
                float2 v0 = {acc[im][in][0] + bx, acc[im][in][1] + by};
                *reinterpret_cast<float2*>(Cf + (size_t)mA * HIDD + n) = v0;
                float2 v1 = {acc[im][in][2] + bx, acc[im][in][3] + by};
                *reinterpret_cast<float2*>(Cf + (size_t)(mA + 8) * HIDD + n) = v1;
            }
    } else {
        uint32_t* chiu = reinterpret_cast<uint32_t*>(ChiB + (size_t)z * MH);
        uint32_t* clou = reinterpret_cast<uint32_t*>(CloB + (size_t)z * MH);
        #pragma unroll
        for (int im = 0; im < 2; im++)
            #pragma unroll
            for (int in = 0; in < 8; in++) {
                const int n = n0 + wn + in * 8 + ec;
                const float bx = bias[n], by = bias[n + 1];
                const int mA = m0 + wm + im * 16 + er;
                float f0 = (acc[im][in][0] + bx) * scale;
                float f1 = (acc[im][in][1] + by) * scale;
                float f2 = (acc[im][in][2] + bx) * scale;
                float f3 = (acc[im][in][3] + by) * scale;
                size_t i0 = ((size_t)mA * HIDD + n) >> 1;
                size_t i1 = ((size_t)(mA + 8) * HIDD + n) >> 1;
                uint32_t h01 = cvt2bf(f0, f1), h23 = cvt2bf(f2, f3);
                chiu[i0] = h01;
                chiu[i1] = h23;
                clou[i0] = cvt2bf(f0 - bflo_f(h01), f1 - bfhi_f(h01));
                clou[i1] = cvt2bf(f2 - bflo_f(h23), f3 - bfhi_f(h23));
            }
    }
}

// ---------------------------------------------------------------------------
// HMMA flash attention: 128 threads / 4 warps, warp tile 32 q-rows x 64 kv.
// 2-stage KV ring, 2 CTAs/SM, ex2-MUFU softmax. ALL 4 nb B-fragments loaded
// up front; MMAs issued term-major across 16 accumulators (reuse distance 16).
// Per-accumulator term order (hh, lh, hl) unchanged -> bitwise identical.
// ---------------------------------------------------------------------------
#define APAD 72
#define SQ_H 0
#define SQ_L (128 * APAD)
#define SKV  (2 * 128 * APAD)
#define KVS_K_L (64 * APAD)
#define KVS_V_H (2 * 64 * APAD)
#define KVS_V_L (3 * 64 * APAD)
#define KV_STG (4 * 64 * APAD)
#define ASMEM_E (SKV + 2 * KV_STG)
#define ASMEM_B (ASMEM_E * 2)              // 110592 bytes
#define TKV (SS / 64)                      // 32

__global__ __launch_bounds__(128, 2) void attn_mma_kernel(
    const __nv_bfloat16* __restrict__ phi, const __nv_bfloat16* __restrict__ plo,
    __nv_bfloat16* __restrict__ chi, __nv_bfloat16* __restrict__ clo)
{
    extern __shared__ __nv_bfloat16 sm[];
    const uint32_t smb = smem_u32(sm);

    const int tid  = threadIdx.x;
    const int wid  = tid >> 5, lane = tid & 31;
    const int b    = blockIdx.y >> 4;
    const int h    = blockIdx.y & 15;
    const int q0   = blockIdx.x * 128;
    const int hoff = h * HDD;

    const __nv_bfloat16* qhi = phi;
    const __nv_bfloat16* qlo = plo;
    const __nv_bfloat16* khi = phi + MH;
    const __nv_bfloat16* klo = plo + MH;
    const __nv_bfloat16* vhi = phi + 2 * MH;
    const __nv_bfloat16* vlo = plo + 2 * MH;

    // ---- Q tile (own commit group; first wait0 covers it)
    {
        const size_t qg = ((size_t)b * SS + q0) * HIDD + hoff;
        #pragma unroll
        for (int i = 0; i < 8; i++) {
            int idx = tid + i * 128;            // 1024: 128 rows x 8 chunks
            int r = idx >> 3, ch = idx & 7;
            cp16(smb + (uint32_t)(SQ_H + r * APAD + ch * 8) * 2,
                 qhi + qg + (size_t)r * HIDD + ch * 8);
            cp16(smb + (uint32_t)(SQ_L + r * APAD + ch * 8) * 2,
                 qlo + qg + (size_t)r * HIDD + ch * 8);
        }
        cp_commit();
    }

    auto issue_kv = [&](int kt) {
        const uint32_t sb = smb + (uint32_t)(SKV + (kt & 1) * KV_STG) * 2;
        #pragma unroll
        for (int i = 0; i < 4; i++) {
            int idx = tid + i * 128;            // 512: 64 rows x 8 chunks
            int r = idx >> 3, ch = idx & 7;
            size_t g = ((size_t)b * SS + kt * 64 + r) * HIDD + hoff + ch * 8;
            uint32_t so = sb + (uint32_t)(r * APAD + ch * 8) * 2;
            cp16(so,                           khi + g);
            cp16(so + (uint32_t)KVS_K_L * 2,   klo + g);
            cp16(so + (uint32_t)KVS_V_H * 2,   vhi + g);
            cp16(so + (uint32_t)KVS_V_L * 2,   vlo + g);
        }
        cp_commit();
    };
    issue_kv(0);

    // warp owns q rows [wid*32, wid*32+32); m-frag im covers +im*16
    const uint32_t aRowOff = (uint32_t)((wid * 32 + (lane & 15)) * APAD +
                                        ((lane >> 4) << 3)) * 2;
    const uint32_t bRowOff = (uint32_t)(((lane & 7) + ((lane & 16) ? 8 : 0)) * APAD +
                                        ((lane & 8) ? 8 : 0)) * 2;
    const uint32_t vRowOff = (uint32_t)((lane & 15) * APAD +
                                        ((lane >> 4) << 3)) * 2;

    float O[2][8][4];
    #pragma unroll
    for (int im = 0; im < 2; im++)
        #pragma unroll
        for (int j = 0; j < 8; j++)
            #pragma unroll
            for (int t = 0; t < 4; t++) O[im][j][t] = 0.f;
    float mrow[2][2] = {{-1e30f, -1e30f}, {-1e30f, -1e30f}};
    float lrow[2][2] = {{0.f, 0.f}, {0.f, 0.f}};

    for (int kt = 0; kt < TKV; kt++) {
        cp_wait0();
        __syncthreads();        // copies visible AND prev-tile readers done
        if (kt + 1 < TKV) issue_kv(kt + 1);

        const uint32_t kvb = smb + (uint32_t)(SKV + (kt & 1) * KV_STG) * 2;

        // ---- S = Q K^T : load ALL K frags, term-major MMA (distance 16)
        float sf[2][8][4];
        #pragma unroll
        for (int im = 0; im < 2; im++)
            #pragma unroll
            for (int j = 0; j < 8; j++)
                #pragma unroll
                for (int t = 0; t < 4; t++) sf[im][j][t] = 0.f;

        #pragma unroll
        for (int kk = 0; kk < 4; kk++) {
            uint32_t qh[2][4], ql[2][4];
            #pragma unroll
            for (int im = 0; im < 2; im++) {
                ldm4(qh[im], smb + (uint32_t)SQ_H * 2 + aRowOff +
                             (uint32_t)(im * 16 * APAD) * 2 + kk * 32);
                ldm4(ql[im], smb + (uint32_t)SQ_L * 2 + aRowOff +
                             (uint32_t)(im * 16 * APAD) * 2 + kk * 32);
            }
            uint32_t rh[4][4], rl[4][4];
            #pragma unroll
            for (int nb = 0; nb < 4; nb++) {
                ldm4(rh[nb], kvb + bRowOff +
                     (uint32_t)(nb * 16 * APAD) * 2 + kk * 32);
                ldm4(rl[nb], kvb + (uint32_t)KVS_K_L * 2 + bRowOff +
                     (uint32_t)(nb * 16 * APAD) * 2 + kk * 32);
            }
            // term 1: qh * Kh  (16 distinct accumulators)
            #pragma unroll
            for (int nb = 0; nb < 4; nb++) {
                uint32_t b0[2] = {rh[nb][0], rh[nb][1]};
                uint32_t b1[2] = {rh[nb][2], rh[nb][3]};
                mma_bf16(sf[0][nb*2],   qh[0], b0);
                mma_bf16(sf[0][nb*2+1], qh[0], b1);
                mma_bf16(sf[1][nb*2],   qh[1], b0);
                mma_bf16(sf[1][nb*2+1], qh[1], b1);
            }
            // term 2: ql * Kh
            #pragma unroll
            for (int nb = 0; nb < 4; nb++) {
                uint32_t b0[2] = {rh[nb][0], rh[nb][1]};
                uint32_t b1[2] = {rh[nb][2], rh[nb][3]};
                mma_bf16(sf[0][nb*2],   ql[0], b0);
                mma_bf16(sf[0][nb*2+1], ql[0], b1);
                mma_bf16(sf[1][nb*2],   ql[1], b0);
                mma_bf16(sf[1][nb*2+1], ql[1], b1);
            }
            // term 3: qh * Kl
            #pragma unroll
            for (int nb = 0; nb < 4; nb++) {
                uint32_t b0[2] = {rl[nb][0], rl[nb][1]};
                uint32_t b1[2] = {rl[nb][2], rl[nb][3]};
                mma_bf16(sf[0][nb*2],   qh[0], b0);
                mma_bf16(sf[0][nb*2+1], qh[0], b1);
                mma_bf16(sf[1][nb*2],   qh[1], b0);
                mma_bf16(sf[1][nb*2+1], qh[1], b1);
            }
        }

        // ---- online softmax (exp2 domain, MUFU ex2), 4 rows per thread
        float cc[2][2];
        #pragma unroll
        for (int im = 0; im < 2; im++) {
            float mx0 = -1e30f, mx1 = -1e30f;
            #pragma unroll
            for (int j = 0; j < 8; j++) {
                mx0 = fmaxf(mx0, fmaxf(sf[im][j][0], sf[im][j][1]));
                mx1 = fmaxf(mx1, fmaxf(sf[im][j][2], sf[im][j][3]));
            }
            mx0 = fmaxf(mx0, __shfl_xor_sync(0xffffffffu, mx0, 1));
            mx0 = fmaxf(mx0, __shfl_xor_sync(0xffffffffu, mx0, 2));
            mx1 = fmaxf(mx1, __shfl_xor_sync(0xffffffffu, mx1, 1));
            mx1 = fmaxf(mx1, __shfl_xor_sync(0xffffffffu, mx1, 2));
            float mn0 = fmaxf(mrow[im][0], mx0);
            float mn1 = fmaxf(mrow[im][1], mx1);
            cc[im][0] = ex2(mrow[im][0] - mn0);
            cc[im][1] = ex2(mrow[im][1] - mn1);
            mrow[im][0] = mn0; mrow[im][1] = mn1;

            float rs0 = 0.f, rs1 = 0.f;
            #pragma unroll
            for (int j = 0; j < 8; j++) {
                sf[im][j][0] = ex2(sf[im][j][0] - mn0);
                sf[im][j][1] = ex2(sf[im][j][1] - mn0);
                sf[im][j][2] = ex2(sf[im][j][2] - mn1);
                sf[im][j][3] = ex2(sf[im][j][3] - mn1);
                rs0 += sf[im][j][0] + sf[im][j][1];
                rs1 += sf[im][j][2] + sf[im][j][3];
            }
            rs0 += __shfl_xor_sync(0xffffffffu, rs0, 1);
            rs0 += __shfl_xor_sync(0xffffffffu, rs0, 2);
            rs1 += __shfl_xor_sync(0xffffffffu, rs1, 1);
            rs1 += __shfl_xor_sync(0xffffffffu, rs1, 2);
            lrow[im][0] = lrow[im][0] * cc[im][0] + rs0;
            lrow[im][1] = lrow[im][1] * cc[im][1] + rs1;
        }

        if (__any_sync(0xffffffffu,
                       (cc[0][0] < 1.f) || (cc[0][1] < 1.f) ||
                       (cc[1][0] < 1.f) || (cc[1][1] < 1.f))) {
            #pragma unroll
            for (int im = 0; im < 2; im++)
                #pragma unroll
                for (int j = 0; j < 8; j++) {
                    O[im][j][0] *= cc[im][0]; O[im][j][1] *= cc[im][0];
                    O[im][j][2] *= cc[im][1]; O[im][j][3] *= cc[im][1];
                }
        }

        // ---- pack P hi/lo into A fragments (cvt.bf16x2-based)
        uint32_t ph01[2][8], ph23[2][8], pl01[2][8], pl23[2][8];
        #pragma unroll
        for (int im = 0; im < 2; im++)
            #pragma unroll
            for (int j = 0; j < 8; j++) {
                uint32_t h01 = cvt2bf(sf[im][j][0], sf[im][j][1]);
                uint32_t h23 = cvt2bf(sf[im][j][2], sf[im][j][3]);
                ph01[im][j] = h01;
                ph23[im][j] = h23;
                pl01[im][j] = cvt2bf(sf[im][j][0] - bflo_f(h01),
                                     sf[im][j][1] - bfhi_f(h01));
                pl23[im][j] = cvt2bf(sf[im][j][2] - bflo_f(h23),
                                     sf[im][j][3] - bfhi_f(h23));
            }

        // ---- O += P V : load ALL V frags, term-major MMA (distance 16)
        #pragma unroll
        for (int kk = 0; kk < 4; kk++) {
            uint32_t ah[2][4], al[2][4];
            #pragma unroll
            for (int im = 0; im < 2; im++) {
                ah[im][0] = ph01[im][2*kk];   ah[im][1] = ph23[im][2*kk];
                ah[im][2] = ph01[im][2*kk+1]; ah[im][3] = ph23[im][2*kk+1];
                al[im][0] = pl01[im][2*kk];   al[im][1] = pl23[im][2*kk];
                al[im][2] = pl01[im][2*kk+1]; al[im][3] = pl23[im][2*kk+1];
            }
            uint32_t rh[4][4], rl[4][4];
            #pragma unroll
            for (int nb = 0; nb < 4; nb++) {
                uint32_t voff = vRowOff + (uint32_t)(kk * 16 * APAD + nb * 16) * 2;
                ldm4t(rh[nb], kvb + (uint32_t)KVS_V_H * 2 + voff);
                ldm4t(rl[nb], kvb + (uint32_t)KVS_V_L * 2 + voff);
            }
            // term 1: Ph * Vh
            #pragma unroll
            for (int nb = 0; nb < 4; nb++) {
                uint32_t b0[2] = {rh[nb][0], rh[nb][1]};
                uint32_t b1[2] = {rh[nb][2], rh[nb][3]};
                mma_bf16(O[0][nb*2],   ah[0], b0);
                mma_bf16(O[0][nb*2+1], ah[0], b1);
                mma_bf16(O[1][nb*2],   ah[1], b0);
                mma_bf16(O[1][nb*2+1], ah[1], b1);
            }
            // term 2: Pl * Vh
            #pragma unroll
            for (int nb = 0; nb < 4; nb++) {
                uint32_t b0[2] = {rh[nb][0], rh[nb][1]};
                uint32_t b1[2] = {rh[nb][2], rh[nb][3]};
                mma_bf16(O[0][nb*2],   al[0], b0);
                mma_bf16(O[0][nb*2+1], al[0], b1);
                mma_bf16(O[1][nb*2],   al[1], b0);
                mma_bf16(O[1][nb*2+1], al[1], b1);
            }
            // term 3: Ph * Vl
            #pragma unroll
            for (int nb = 0; nb < 4; nb++) {
                uint32_t b0[2] = {rl[nb][0], rl[nb][1]};
                uint32_t b1[2] = {rl[nb][2], rl[nb][3]};
                mma_bf16(O[0][nb*2],   ah[0], b0);
                mma_bf16(O[0][nb*2+1], ah[0], b1);
                mma_bf16(O[1][nb*2],   ah[1], b0);
                mma_bf16(O[1][nb*2+1], ah[1], b1);
            }
        }
        // no end-of-loop barrier: next iteration's top barrier orders
        // stage overwrite (distance-1 issue) against this tile's readers
    }

    // ---- epilogue: ctx hi/lo (cvt-based)
    const int er = lane >> 2, ec = (lane & 3) * 2;
    uint32_t* chiu = reinterpret_cast<uint32_t*>(chi);
    uint32_t* clou = reinterpret_cast<uint32_t*>(clo);
    #pragma unroll
    for (int im = 0; im < 2; im++) {
        const float inv0 = 1.f / lrow[im][0], inv1 = 1.f / lrow[im][1];
        const int row0 = q0 + wid * 32 + im * 16 + er;
        #pragma unroll
        for (int j = 0; j < 8; j++) {
            const int col = hoff + j * 8 + ec;
            float f0 = O[im][j][0] * inv0, f1 = O[im][j][1] * inv0;
            float f2 = O[im][j][2] * inv1, f3 = O[im][j][3] * inv1;
            size_t i0 = (((size_t)b * SS + row0) * HIDD + col) >> 1;
            size_t i1 = (((size_t)b * SS + row0 + 8) * HIDD + col) >> 1;
            uint32_t h01 = cvt2bf(f0, f1), h23 = cvt2bf(f2, f3);
            chiu[i0] = h01;
            chiu[i1] = h23;
            clou[i0] = cvt2bf(f0 - bflo_f(h01), f1 - bfhi_f(h01));
            clou[i1] = cvt2bf(f2 - bflo_f(h23), f3 - bfhi_f(h23));
        }
    }
}

// ---------------------------------------------------------------------------

extern "C" void kernel_launch(void* const* d_in, const int* in_sizes, int n_in,
                              void* d_out, int out_size)
{
    const float* query = (const float*)d_in[0];
    const float* key_  = (const float*)d_in[1];
    const float* value = (const float*)d_in[2];
    const float* Wq    = (const float*)d_in[3];
    const float* bq    = (const float*)d_in[4];
    const float* Wk    = (const float*)d_in[5];
    const float* bk    = (const float*)d_in[6];
    const float* Wv    = (const float*)d_in[7];
    const float* bv    = (const float*)d_in[8];
    const float* Wo    = (const float*)d_in[9];
    const float* bo    = (const float*)d_in[10];
    float* out = (float*)d_out;

    __nv_bfloat16 *inhi, *inlo, *wthi, *wtlo, *phi, *plo, *chi, *clo;
    cudaGetSymbolAddress((void**)&inhi, g_inhi);
    cudaGetSymbolAddress((void**)&inlo, g_inlo);
    cudaGetSymbolAddress((void**)&wthi, g_wthi);
    cudaGetSymbolAddress((void**)&wtlo, g_wtlo);
    cudaGetSymbolAddress((void**)&phi, g_phi);
    cudaGetSymbolAddress((void**)&plo, g_plo);
    cudaGetSymbolAddress((void**)&chi, g_chi);
    cudaGetSymbolAddress((void**)&clo, g_clo);

    cudaFuncSetAttribute(mma_gemm_kernel,
                         cudaFuncAttributeMaxDynamicSharedMemorySize, GSMEM);
    cudaFuncSetAttribute(attn_mma_kernel,
                         cudaFuncAttributeMaxDynamicSharedMemorySize, ASMEM_B);

    const int n4 = (int)(MH / 4);
    const float qscale = 0.125f * 1.44269504088896f;  // 1/sqrt(HD) * log2(e)

    split3_kernel<<<dim3(n4 / 256, 3), 256>>>(query, key_, value, inhi, inlo, n4);
    splitT4_kernel<<<dim3(32, 32, 4), 256>>>(Wq, Wk, Wv, Wo, wthi, wtlo);

    // Q,K,V projections (grid.z = 3), 128x128 tiles
    mma_gemm_kernel<<<dim3(HIDD / 128, MM / 128, 3), 256, GSMEM>>>(
        inhi, inlo, wthi, wtlo, bq, bk, bv,
        nullptr, phi, plo, 1, qscale);

    attn_mma_kernel<<<dim3(SS / 128, BB * NHH), 128, ASMEM_B>>>(phi, plo, chi, clo);

    // output projection (weight slot 3, fp32 out)
    mma_gemm_kernel<<<dim3(HIDD / 128, MM / 128, 1), 256, GSMEM>>>(
        chi, clo, wthi + 3 * HH, wtlo + 3 * HH, bo, bo, bo,
        out, nullptr, nullptr, 0, 1.0f);
}